// round 1
// baseline (speedup 1.0000x reference)
#include <cuda_runtime.h>
#include <cstdint>

// ---------------- problem constants ----------------
#define BDIM     4
#define SEQ      8192
#define CDIM     512
#define NH       8
#define HD       64
#define NLM      64
#define LMSTRIDE 128           // SEQ / NLM
#define BN_TOK   (BDIM*SEQ)    // 32768
#define QKV_N    (3*CDIM)      // 1536
#define NBH      (BDIM*NH)     // 32
#define NCH      32            // key chunks for kernel_3 flash
#define KEYS_PER_CH (SEQ/NCH)  // 256
#define TILES_PER_CH (KEYS_PER_CH/64) // 4
#define SCALE    0.125f        // hd^-0.5

// ---------------- device scratch (no runtime allocs allowed) ----------------
__device__ float gY [(size_t)BN_TOK * QKV_N];   // qkv activations, [B*N,1536]
__device__ float gAT[(size_t)BN_TOK * CDIM];    // attention output, [B*N,512]
__device__ float gW2inv[NBH*64*64];
__device__ float gT    [NBH*64*64];             // W2inv @ F
__device__ float gFp[(size_t)NBH*NCH*64*64];    // flash partial accumulators
__device__ float gMp[NBH*NCH*64];
__device__ float gSp[NBH*NCH*64];

// ---------------- small 64x64 matmul helpers (4x4 register tiles) -----------
__device__ __forceinline__ void mm64_nt(float* C, int ldc,
                                        const float* A, int lda,
                                        const float* B, int ldb,
                                        float scale, int tid)
{
    // C[i][j] = scale * sum_d A[i][d] * B[j][d]
    const int i0 = (tid >> 4) * 4, j0 = (tid & 15) * 4;
    float c[4][4] = {};
    #pragma unroll 8
    for (int d = 0; d < 64; d++) {
        float a[4], bv[4];
        #pragma unroll
        for (int ii = 0; ii < 4; ii++) a[ii]  = A[(i0+ii)*lda + d];
        #pragma unroll
        for (int jj = 0; jj < 4; jj++) bv[jj] = B[(j0+jj)*ldb + d];
        #pragma unroll
        for (int ii = 0; ii < 4; ii++)
            #pragma unroll
            for (int jj = 0; jj < 4; jj++)
                c[ii][jj] += a[ii] * bv[jj];
    }
    #pragma unroll
    for (int ii = 0; ii < 4; ii++)
        #pragma unroll
        for (int jj = 0; jj < 4; jj++)
            C[(i0+ii)*ldc + j0+jj] = scale * c[ii][jj];
}

__device__ __forceinline__ void mm64_nn(float* C, int ldc,
                                        const float* A, int lda,
                                        const float* B, int ldb, int tid)
{
    // C[i][j] = sum_k A[i][k] * B[k][j]
    const int i0 = (tid >> 4) * 4, j0 = (tid & 15) * 4;
    float c[4][4] = {};
    #pragma unroll 8
    for (int k = 0; k < 64; k++) {
        float a[4], bv[4];
        #pragma unroll
        for (int ii = 0; ii < 4; ii++) a[ii]  = A[(i0+ii)*lda + k];
        #pragma unroll
        for (int jj = 0; jj < 4; jj++) bv[jj] = B[k*ldb + j0+jj];
        #pragma unroll
        for (int ii = 0; ii < 4; ii++)
            #pragma unroll
            for (int jj = 0; jj < 4; jj++)
                c[ii][jj] += a[ii] * bv[jj];
    }
    #pragma unroll
    for (int ii = 0; ii < 4; ii++)
        #pragma unroll
        for (int jj = 0; jj < 4; jj++)
            C[(i0+ii)*ldc + j0+jj] = c[ii][jj];
}

// ---------------- big fp32 GEMM: C[M,N] = A[M,K] @ B[N,K]^T + bias ----------
__global__ void __launch_bounds__(256) gemm_nt(const float* __restrict__ A,
                                               const float* __restrict__ B,
                                               const float* __restrict__ bias,
                                               float* __restrict__ C,
                                               int M, int N, int K)
{
    __shared__ float As[16][128];
    __shared__ float Bs[16][128];
    const int bm = blockIdx.y * 128;
    const int bn = blockIdx.x * 128;
    const int tid = threadIdx.x;
    const int tx = tid & 15;
    const int ty = tid >> 4;

    float acc[8][8];
    #pragma unroll
    for (int i = 0; i < 8; i++)
        #pragma unroll
        for (int j = 0; j < 8; j++) acc[i][j] = 0.f;

    for (int k0 = 0; k0 < K; k0 += 16) {
        #pragma unroll
        for (int i = 0; i < 2; i++) {
            int idx = tid + i * 256;         // 0..511
            int r  = idx >> 2;               // 0..127
            int kv = (idx & 3) << 2;         // 0,4,8,12
            float4 av = *(const float4*)(A + (size_t)(bm + r) * K + k0 + kv);
            As[kv+0][r] = av.x; As[kv+1][r] = av.y; As[kv+2][r] = av.z; As[kv+3][r] = av.w;
            float4 bv = *(const float4*)(B + (size_t)(bn + r) * K + k0 + kv);
            Bs[kv+0][r] = bv.x; Bs[kv+1][r] = bv.y; Bs[kv+2][r] = bv.z; Bs[kv+3][r] = bv.w;
        }
        __syncthreads();
        #pragma unroll
        for (int kk = 0; kk < 16; kk++) {
            float a[8], b[8];
            *(float4*)&a[0] = *(const float4*)&As[kk][ty * 4];
            *(float4*)&a[4] = *(const float4*)&As[kk][64 + ty * 4];
            *(float4*)&b[0] = *(const float4*)&Bs[kk][tx * 4];
            *(float4*)&b[4] = *(const float4*)&Bs[kk][64 + tx * 4];
            #pragma unroll
            for (int i = 0; i < 8; i++)
                #pragma unroll
                for (int j = 0; j < 8; j++)
                    acc[i][j] += a[i] * b[j];
        }
        __syncthreads();
    }

    #pragma unroll
    for (int i = 0; i < 8; i++) {
        int row = bm + ((i < 4) ? (ty * 4 + i) : (64 + ty * 4 + (i - 4)));
        #pragma unroll
        for (int jh = 0; jh < 2; jh++) {
            int col = bn + jh * 64 + tx * 4;
            float4 o;
            o.x = acc[i][jh*4+0] + bias[col+0];
            o.y = acc[i][jh*4+1] + bias[col+1];
            o.z = acc[i][jh*4+2] + bias[col+2];
            o.w = acc[i][jh*4+3] + bias[col+3];
            *(float4*)(C + (size_t)row * N + col) = o;
        }
    }
}

// ---------------- kernel_2 softmax + Newton pseudo-inverse -------------------
// one block per (b,h). S,Z,T1,T2 are 64x64 (stride 65) in dynamic smem.
__global__ void __launch_bounds__(256) k2_newton()
{
    extern __shared__ float sm2[];
    float* S  = sm2;
    float* Z  = S  + 4160;
    float* T1 = Z  + 4160;
    float* T2 = T1 + 4160;
    __shared__ float red[8];

    const int bh = blockIdx.x;
    const int b = bh >> 3, h = bh & 7;
    const int tid = threadIdx.x;

    // load q_lm into Z, k_lm into T1
    for (int e = tid; e < 4096; e += 256) {
        int l = e >> 6, d = e & 63;
        size_t base = (size_t)(b * SEQ + l * LMSTRIDE) * QKV_N + h * HD + d;
        Z [l*65 + d] = gY[base];
        T1[l*65 + d] = gY[base + CDIM];
    }
    __syncthreads();

    // S = softmax_rows(scale * Q_lm K_lm^T)
    mm64_nt(S, 65, Z, 65, T1, 65, SCALE, tid);
    __syncthreads();
    if (tid < 64) {
        float mx = -1e30f;
        for (int j = 0; j < 64; j++) mx = fmaxf(mx, S[tid*65 + j]);
        float s = 0.f;
        for (int j = 0; j < 64; j++) { float p = __expf(S[tid*65+j] - mx); S[tid*65+j] = p; s += p; }
        float inv = 1.f / s;
        for (int j = 0; j < 64; j++) S[tid*65 + j] *= inv;
    }
    __syncthreads();

    // fro^2
    float part = 0.f;
    for (int e = tid; e < 4096; e += 256) {
        int i = e >> 6, j = e & 63;
        float v = S[i*65 + j];
        part += v * v;
    }
    #pragma unroll
    for (int o = 16; o; o >>= 1) part += __shfl_xor_sync(0xffffffffu, part, o);
    if ((tid & 31) == 0) red[tid >> 5] = part;
    __syncthreads();
    float fro2 = red[0]+red[1]+red[2]+red[3]+red[4]+red[5]+red[6]+red[7];
    fro2 = fmaxf(fro2, 1e-12f);
    float invf = 1.f / fro2;

    // Z = S^T / fro^2
    for (int e = tid; e < 4096; e += 256) {
        int i = e >> 6, j = e & 63;
        Z[j*65 + i] = S[i*65 + j] * invf;
    }
    __syncthreads();

    for (int it = 0; it < 6; it++) {
        mm64_nn(T1, 65, S, 65, Z, 65, tid);   // T1 = S @ Z
        __syncthreads();
        mm64_nn(T2, 65, Z, 65, T1, 65, tid);  // T2 = Z @ T1
        __syncthreads();
        for (int e = tid; e < 4096; e += 256) {
            int i = e >> 6, j = e & 63;
            Z[i*65 + j] = 2.f * Z[i*65 + j] - T2[i*65 + j];
        }
        __syncthreads();
    }

    for (int e = tid; e < 4096; e += 256) {
        int i = e >> 6, j = e & 63;
        gW2inv[bh*4096 + i*64 + j] = Z[i*65 + j];
    }
}

// ---------------- kernel_3 flash: softmax(q_lm k^T) @ v, partials ------------
// grid (NBH, NCH), block 256
__global__ void __launch_bounds__(256) k3_flash()
{
    extern __shared__ float sm3[];
    float* sQ  = sm3;           // 64*64
    float* sK  = sQ + 4096;     // 64*65
    float* sV  = sK + 4160;     // 64*64
    float* sS  = sV + 4096;     // 64*65
    float* m_s = sS + 4160;     // 64
    float* s_s = m_s + 64;
    float* c_s = s_s + 64;

    const int bh = blockIdx.x;
    const int ch = blockIdx.y;
    const int b = bh >> 3, h = bh & 7;
    const int tid = threadIdx.x;
    const int i0 = (tid >> 4) * 4, d0 = (tid & 15) * 4;

    for (int e = tid; e < 4096; e += 256) {
        int l = e >> 6, d = e & 63;
        sQ[l*64 + d] = gY[(size_t)(b * SEQ + l * LMSTRIDE) * QKV_N + h * HD + d];
    }
    if (tid < 64) { m_s[tid] = -1e30f; s_s[tid] = 0.f; }
    float acc[4][4] = {};
    __syncthreads();

    for (int t = 0; t < TILES_PER_CH; t++) {
        int n0 = ch * KEYS_PER_CH + t * 64;
        for (int e = tid; e < 4096; e += 256) {
            int j = e >> 6, d = e & 63;
            size_t base = (size_t)(b * SEQ + n0 + j) * QKV_N + h * HD + d;
            sK[j*65 + d] = gY[base + CDIM];
            sV[j*64 + d] = gY[base + 2*CDIM];
        }
        __syncthreads();
        mm64_nt(sS, 65, sQ, 64, sK, 65, SCALE, tid);
        __syncthreads();
        if (tid < 64) {
            float tmax = -1e30f;
            for (int j = 0; j < 64; j++) tmax = fmaxf(tmax, sS[tid*65 + j]);
            float mnew = fmaxf(m_s[tid], tmax);
            float corr = __expf(m_s[tid] - mnew);
            float rsum = 0.f;
            for (int j = 0; j < 64; j++) {
                float p = __expf(sS[tid*65 + j] - mnew);
                sS[tid*65 + j] = p;
                rsum += p;
            }
            s_s[tid] = s_s[tid] * corr + rsum;
            c_s[tid] = corr;
            m_s[tid] = mnew;
        }
        __syncthreads();
        #pragma unroll
        for (int ii = 0; ii < 4; ii++) {
            int l = i0 + ii;
            float corr = c_s[l];
            float r0 = acc[ii][0]*corr, r1 = acc[ii][1]*corr,
                  r2 = acc[ii][2]*corr, r3 = acc[ii][3]*corr;
            #pragma unroll 8
            for (int j = 0; j < 64; j++) {
                float p = sS[l*65 + j];
                float4 v = *(const float4*)&sV[j*64 + d0];
                r0 += p*v.x; r1 += p*v.y; r2 += p*v.z; r3 += p*v.w;
            }
            acc[ii][0]=r0; acc[ii][1]=r1; acc[ii][2]=r2; acc[ii][3]=r3;
        }
        __syncthreads();
    }

    size_t base = ((size_t)bh * NCH + ch) * 4096;
    #pragma unroll
    for (int ii = 0; ii < 4; ii++)
        *(float4*)&gFp[base + (size_t)(i0+ii)*64 + d0] =
            make_float4(acc[ii][0], acc[ii][1], acc[ii][2], acc[ii][3]);
    if (tid < 64) {
        gMp[(bh*NCH + ch)*64 + tid] = m_s[tid];
        gSp[(bh*NCH + ch)*64 + tid] = s_s[tid];
    }
}

// ---------------- combine flash partials + T = W2inv @ F --------------------
__global__ void __launch_bounds__(256) k3_combine()
{
    __shared__ float wgt[NCH*64];
    __shared__ float sF[64*65];
    __shared__ float sW[64*64];
    const int bh = blockIdx.x;
    const int tid = threadIdx.x;

    if (tid < 64) {
        float M = -1e30f;
        for (int c = 0; c < NCH; c++) M = fmaxf(M, gMp[(bh*NCH + c)*64 + tid]);
        float denom = 0.f;
        for (int c = 0; c < NCH; c++)
            denom += __expf(gMp[(bh*NCH + c)*64 + tid] - M) * gSp[(bh*NCH + c)*64 + tid];
        float invd = 1.f / denom;
        for (int c = 0; c < NCH; c++)
            wgt[c*64 + tid] = __expf(gMp[(bh*NCH + c)*64 + tid] - M) * invd;
    }
    for (int e = tid; e < 4096; e += 256) sW[e] = gW2inv[bh*4096 + e];
    __syncthreads();

    for (int e = tid; e < 4096; e += 256) {
        int l = e >> 6, d = e & 63;
        float f = 0.f;
        for (int c = 0; c < NCH; c++)
            f += gFp[((size_t)bh * NCH + c) * 4096 + e] * wgt[c*64 + l];
        sF[l*65 + d] = f;
    }
    __syncthreads();

    // T = W2inv @ F
    const int i0 = (tid >> 4) * 4, j0 = (tid & 15) * 4;
    float c[4][4] = {};
    #pragma unroll 8
    for (int k = 0; k < 64; k++) {
        float a[4], bv[4];
        #pragma unroll
        for (int ii = 0; ii < 4; ii++) a[ii] = sW[(i0+ii)*64 + k];
        #pragma unroll
        for (int jj = 0; jj < 4; jj++) bv[jj] = sF[k*65 + j0+jj];
        #pragma unroll
        for (int ii = 0; ii < 4; ii++)
            #pragma unroll
            for (int jj = 0; jj < 4; jj++)
                c[ii][jj] += a[ii] * bv[jj];
    }
    #pragma unroll
    for (int ii = 0; ii < 4; ii++)
        #pragma unroll
        for (int jj = 0; jj < 4; jj++)
            gT[bh*4096 + (i0+ii)*64 + j0+jj] = c[ii][jj];
}

// ---------------- kernel_1 @ T -> attention output ---------------------------
// grid (128 q-tiles, NBH), block 256
__global__ void __launch_bounds__(256) k4_out()
{
    extern __shared__ float sm4[];
    float* sK = sm4;            // 64*65 k_lm
    float* sT = sK + 4160;      // 64*64
    float* sQ = sT + 4096;      // 64*64
    float* sS = sQ + 4096;      // 64*65

    const int bh = blockIdx.y;
    const int qt = blockIdx.x;
    const int b = bh >> 3, h = bh & 7;
    const int n0 = qt * 64;
    const int tid = threadIdx.x;

    for (int e = tid; e < 4096; e += 256) {
        int l = e >> 6, d = e & 63;
        sK[l*65 + d] = gY[(size_t)(b * SEQ + l * LMSTRIDE) * QKV_N + CDIM + h * HD + d];
        sT[l*64 + d] = gT[bh*4096 + e];
        sQ[l*64 + d] = gY[(size_t)(b * SEQ + n0 + l) * QKV_N + h * HD + d];
    }
    __syncthreads();

    mm64_nt(sS, 65, sQ, 64, sK, 65, SCALE, tid);
    __syncthreads();
    if (tid < 64) {
        float mx = -1e30f;
        for (int j = 0; j < 64; j++) mx = fmaxf(mx, sS[tid*65 + j]);
        float s = 0.f;
        for (int j = 0; j < 64; j++) { float p = __expf(sS[tid*65+j] - mx); sS[tid*65+j] = p; s += p; }
        float inv = 1.f / s;
        for (int j = 0; j < 64; j++) sS[tid*65 + j] *= inv;
    }
    __syncthreads();

    const int i0 = (tid >> 4) * 4, d0 = (tid & 15) * 4;
    float c[4][4] = {};
    #pragma unroll 8
    for (int l = 0; l < 64; l++) {
        float a[4];
        #pragma unroll
        for (int ii = 0; ii < 4; ii++) a[ii] = sS[(i0+ii)*65 + l];
        float4 tv = *(const float4*)&sT[l*64 + d0];
        #pragma unroll
        for (int ii = 0; ii < 4; ii++) {
            c[ii][0] += a[ii]*tv.x; c[ii][1] += a[ii]*tv.y;
            c[ii][2] += a[ii]*tv.z; c[ii][3] += a[ii]*tv.w;
        }
    }
    #pragma unroll
    for (int ii = 0; ii < 4; ii++)
        *(float4*)&gAT[(size_t)(b * SEQ + n0 + i0 + ii) * CDIM + h * HD + d0] =
            make_float4(c[ii][0], c[ii][1], c[ii][2], c[ii][3]);
}

// ---------------- launcher ---------------------------------------------------
extern "C" void kernel_launch(void* const* d_in, const int* in_sizes, int n_in,
                              void* d_out, int out_size)
{
    const float* x     = (const float*)d_in[0];
    const float* Wqkv  = (const float*)d_in[1];
    const float* bqkv  = (const float*)d_in[2];
    const float* Wproj = (const float*)d_in[3];
    const float* bproj = (const float*)d_in[4];
    float* out = (float*)d_out;

    const int SMEM_K2 = 4 * 4160 * 4;                              // 66560
    const int SMEM_K3 = (4096 + 4160 + 4096 + 4160 + 192) * 4;     // 66816
    const int SMEM_K4 = (4160 + 4096 + 4096 + 4160) * 4;           // 66048
    cudaFuncSetAttribute(k2_newton, cudaFuncAttributeMaxDynamicSharedMemorySize, SMEM_K2);
    cudaFuncSetAttribute(k3_flash,  cudaFuncAttributeMaxDynamicSharedMemorySize, SMEM_K3);
    cudaFuncSetAttribute(k4_out,    cudaFuncAttributeMaxDynamicSharedMemorySize, SMEM_K4);

    float *pY, *pAT;
    cudaGetSymbolAddress((void**)&pY,  gY);
    cudaGetSymbolAddress((void**)&pAT, gAT);

    // 1. QKV projection: gY = x @ Wqkv^T + bqkv
    gemm_nt<<<dim3(QKV_N/128, BN_TOK/128), 256>>>(x, Wqkv, bqkv, pY, BN_TOK, QKV_N, CDIM);
    // 2. kernel_2 softmax + Newton inverse
    k2_newton<<<NBH, 256, SMEM_K2>>>();
    // 3. kernel_3 flash softmax @ v (partials), then combine + T = W2inv @ F
    k3_flash<<<dim3(NBH, NCH), 256, SMEM_K3>>>();
    k3_combine<<<NBH, 256>>>();
    // 4. out = softmax(q k_lm^T) @ T  -> gAT in [B,N,C] layout
    k4_out<<<dim3(SEQ/64, NBH), 256, SMEM_K4>>>();
    // 5. projection: out = gAT @ Wproj^T + bproj
    gemm_nt<<<dim3(CDIM/128, BN_TOK/128), 256>>>(pAT, Wproj, bproj, out, BN_TOK, CDIM, CDIM);
}

// round 2
// speedup vs baseline: 1.8011x; 1.8011x over previous
#include <cuda_runtime.h>
#include <cstdint>

// ---------------- problem constants ----------------
#define BDIM     4
#define SEQ      8192
#define CDIM     512
#define NH       8
#define HD       64
#define NLM      64
#define LMSTRIDE 128           // SEQ / NLM
#define BN_TOK   (BDIM*SEQ)    // 32768
#define QKV_N    (3*CDIM)      // 1536
#define NBH      (BDIM*NH)     // 32
#define NCH      32            // key chunks for kernel_3 flash
#define KEYS_PER_CH (SEQ/NCH)  // 256
#define TILES_PER_CH (KEYS_PER_CH/64) // 4
#define SCALE    0.125f        // hd^-0.5

// ---------------- device scratch (no runtime allocs allowed) ----------------
__device__ float gY [(size_t)BN_TOK * QKV_N];   // qkv activations, [B*N,1536]
__device__ float gAT[(size_t)BN_TOK * CDIM];    // attention output, [B*N,512]
__device__ float gW2inv[NBH*64*64];
__device__ float gT    [NBH*64*64];             // W2inv @ F
__device__ float gFp[(size_t)NBH*NCH*64*64];    // flash partial accumulators
__device__ float gMp[NBH*NCH*64];
__device__ float gSp[NBH*NCH*64];

// ---------------- tf32 helpers ----------------------------------------------
__device__ __forceinline__ uint32_t f2tf32(float f) {
    uint32_t u;
    asm("cvt.rna.tf32.f32 %0, %1;" : "=r"(u) : "f"(f));
    return u;
}

__device__ __forceinline__ void mma_tf32(float* d, const uint32_t* a, const uint32_t* b) {
    asm volatile(
        "mma.sync.aligned.m16n8k8.row.col.f32.tf32.tf32.f32 "
        "{%0,%1,%2,%3}, {%4,%5,%6,%7}, {%8,%9}, {%0,%1,%2,%3};"
        : "+f"(d[0]), "+f"(d[1]), "+f"(d[2]), "+f"(d[3])
        : "r"(a[0]), "r"(a[1]), "r"(a[2]), "r"(a[3]),
          "r"(b[0]), "r"(b[1]));
}

// ---------------- tf32 tensor-core GEMM: C = A[M,K] @ B[N,K]^T + bias -------
// block 128x128, 256 threads (8 warps of 64x32), double-buffered K16 stages.
#define LDSA 20  // floats per smem row (16 + 4 pad) -> conflict-free frag loads

__device__ __forceinline__ void st_stage(uint32_t* s, int row, int kq, float4 v) {
    uint32_t* p = s + row * LDSA + kq;
    p[0] = f2tf32(v.x); p[1] = f2tf32(v.y); p[2] = f2tf32(v.z); p[3] = f2tf32(v.w);
}

__global__ void __launch_bounds__(256) gemm_tf32(const float* __restrict__ A,
                                                 const float* __restrict__ B,
                                                 const float* __restrict__ bias,
                                                 float* __restrict__ C,
                                                 int M, int N, int K)
{
    __shared__ uint32_t As[2][128 * LDSA];
    __shared__ uint32_t Bs[2][128 * LDSA];

    const int bm = blockIdx.y * 128;
    const int bn = blockIdx.x * 128;
    const int tid  = threadIdx.x;
    const int lane = tid & 31;
    const int warp = tid >> 5;
    const int wm = (warp & 1) * 64;   // warp M offset
    const int wn = (warp >> 1) * 32;  // warp N offset
    const int g = lane >> 2;          // groupID 0..7
    const int c = lane & 3;           // thread-in-group 0..3

    // staging: each thread loads 2 float4 from A and 2 from B per stage
    const int r0 = tid >> 2;          // 0..63
    const int kq = (tid & 3) * 4;     // 0,4,8,12

    float acc[4][4][4];
    #pragma unroll
    for (int mi = 0; mi < 4; mi++)
        #pragma unroll
        for (int ni = 0; ni < 4; ni++)
            #pragma unroll
            for (int r = 0; r < 4; r++) acc[mi][ni][r] = 0.f;

    const float* Ap = A + (size_t)(bm + r0) * K + kq;
    const float* Bp = B + (size_t)(bn + r0) * K + kq;
    const size_t arow64 = (size_t)64 * K;

    // prologue: stage 0
    {
        float4 a0v = *(const float4*)(Ap);
        float4 a1v = *(const float4*)(Ap + arow64);
        float4 b0v = *(const float4*)(Bp);
        float4 b1v = *(const float4*)(Bp + arow64);
        st_stage(As[0], r0,      kq, a0v);
        st_stage(As[0], r0 + 64, kq, a1v);
        st_stage(Bs[0], r0,      kq, b0v);
        st_stage(Bs[0], r0 + 64, kq, b1v);
    }

    const int KT = K >> 4;
    for (int kt = 0; kt < KT; kt++) {
        __syncthreads();

        float4 na0, na1, nb0, nb1;
        const bool more = (kt + 1 < KT);
        if (more) {
            const float* ap = Ap + (kt + 1) * 16;
            const float* bp = Bp + (kt + 1) * 16;
            na0 = *(const float4*)(ap);
            na1 = *(const float4*)(ap + arow64);
            nb0 = *(const float4*)(bp);
            nb1 = *(const float4*)(bp + arow64);
        }

        const int buf = kt & 1;
        const uint32_t* as = As[buf];
        const uint32_t* bs = Bs[buf];

        #pragma unroll
        for (int ks = 0; ks < 2; ks++) {
            const int kb = ks * 8;
            uint32_t af[4][4], bf[4][2];
            #pragma unroll
            for (int mi = 0; mi < 4; mi++) {
                const int row = wm + mi * 16 + g;
                af[mi][0] = as[row * LDSA + kb + c];
                af[mi][1] = as[(row + 8) * LDSA + kb + c];
                af[mi][2] = as[row * LDSA + kb + c + 4];
                af[mi][3] = as[(row + 8) * LDSA + kb + c + 4];
            }
            #pragma unroll
            for (int ni = 0; ni < 4; ni++) {
                const int col = wn + ni * 8 + g;
                bf[ni][0] = bs[col * LDSA + kb + c];
                bf[ni][1] = bs[col * LDSA + kb + c + 4];
            }
            #pragma unroll
            for (int mi = 0; mi < 4; mi++)
                #pragma unroll
                for (int ni = 0; ni < 4; ni++)
                    mma_tf32(acc[mi][ni], af[mi], bf[ni]);
        }

        if (more) {
            const int nbuf = buf ^ 1;
            st_stage(As[nbuf], r0,      kq, na0);
            st_stage(As[nbuf], r0 + 64, kq, na1);
            st_stage(Bs[nbuf], r0,      kq, nb0);
            st_stage(Bs[nbuf], r0 + 64, kq, nb1);
        }
    }

    // epilogue: C[row, col] = acc + bias[col]
    #pragma unroll
    for (int mi = 0; mi < 4; mi++) {
        const int row = bm + wm + mi * 16 + g;
        #pragma unroll
        for (int ni = 0; ni < 4; ni++) {
            const int col = bn + wn + ni * 8 + 2 * c;
            const float b0 = bias[col], b1 = bias[col + 1];
            float2 o0 = make_float2(acc[mi][ni][0] + b0, acc[mi][ni][1] + b1);
            float2 o1 = make_float2(acc[mi][ni][2] + b0, acc[mi][ni][3] + b1);
            *(float2*)(C + (size_t)row * N + col)       = o0;
            *(float2*)(C + (size_t)(row + 8) * N + col) = o1;
        }
    }
}

// ---------------- small 64x64 matmul helpers (4x4 register tiles) -----------
__device__ __forceinline__ void mm64_nt(float* C, int ldc,
                                        const float* A, int lda,
                                        const float* B, int ldb,
                                        float scale, int tid)
{
    const int i0 = (tid >> 4) * 4, j0 = (tid & 15) * 4;
    float c[4][4] = {};
    #pragma unroll 8
    for (int d = 0; d < 64; d++) {
        float a[4], bv[4];
        #pragma unroll
        for (int ii = 0; ii < 4; ii++) a[ii]  = A[(i0+ii)*lda + d];
        #pragma unroll
        for (int jj = 0; jj < 4; jj++) bv[jj] = B[(j0+jj)*ldb + d];
        #pragma unroll
        for (int ii = 0; ii < 4; ii++)
            #pragma unroll
            for (int jj = 0; jj < 4; jj++)
                c[ii][jj] += a[ii] * bv[jj];
    }
    #pragma unroll
    for (int ii = 0; ii < 4; ii++)
        #pragma unroll
        for (int jj = 0; jj < 4; jj++)
            C[(i0+ii)*ldc + j0+jj] = scale * c[ii][jj];
}

__device__ __forceinline__ void mm64_nn(float* C, int ldc,
                                        const float* A, int lda,
                                        const float* B, int ldb, int tid)
{
    const int i0 = (tid >> 4) * 4, j0 = (tid & 15) * 4;
    float c[4][4] = {};
    #pragma unroll 8
    for (int k = 0; k < 64; k++) {
        float a[4], bv[4];
        #pragma unroll
        for (int ii = 0; ii < 4; ii++) a[ii]  = A[(i0+ii)*lda + k];
        #pragma unroll
        for (int jj = 0; jj < 4; jj++) bv[jj] = B[k*ldb + j0+jj];
        #pragma unroll
        for (int ii = 0; ii < 4; ii++)
            #pragma unroll
            for (int jj = 0; jj < 4; jj++)
                c[ii][jj] += a[ii] * bv[jj];
    }
    #pragma unroll
    for (int ii = 0; ii < 4; ii++)
        #pragma unroll
        for (int jj = 0; jj < 4; jj++)
            C[(i0+ii)*ldc + j0+jj] = c[ii][jj];
}

// ---------------- kernel_2 softmax + Newton pseudo-inverse -------------------
__global__ void __launch_bounds__(256) k2_newton()
{
    extern __shared__ float sm2[];
    float* S  = sm2;
    float* Z  = S  + 4160;
    float* T1 = Z  + 4160;
    float* T2 = T1 + 4160;
    __shared__ float red[8];

    const int bh = blockIdx.x;
    const int b = bh >> 3, h = bh & 7;
    const int tid = threadIdx.x;

    for (int e = tid; e < 4096; e += 256) {
        int l = e >> 6, d = e & 63;
        size_t base = (size_t)(b * SEQ + l * LMSTRIDE) * QKV_N + h * HD + d;
        Z [l*65 + d] = gY[base];
        T1[l*65 + d] = gY[base + CDIM];
    }
    __syncthreads();

    mm64_nt(S, 65, Z, 65, T1, 65, SCALE, tid);
    __syncthreads();
    if (tid < 64) {
        float mx = -1e30f;
        for (int j = 0; j < 64; j++) mx = fmaxf(mx, S[tid*65 + j]);
        float s = 0.f;
        for (int j = 0; j < 64; j++) { float p = __expf(S[tid*65+j] - mx); S[tid*65+j] = p; s += p; }
        float inv = 1.f / s;
        for (int j = 0; j < 64; j++) S[tid*65 + j] *= inv;
    }
    __syncthreads();

    float part = 0.f;
    for (int e = tid; e < 4096; e += 256) {
        int i = e >> 6, j = e & 63;
        float v = S[i*65 + j];
        part += v * v;
    }
    #pragma unroll
    for (int o = 16; o; o >>= 1) part += __shfl_xor_sync(0xffffffffu, part, o);
    if ((tid & 31) == 0) red[tid >> 5] = part;
    __syncthreads();
    float fro2 = red[0]+red[1]+red[2]+red[3]+red[4]+red[5]+red[6]+red[7];
    fro2 = fmaxf(fro2, 1e-12f);
    float invf = 1.f / fro2;

    for (int e = tid; e < 4096; e += 256) {
        int i = e >> 6, j = e & 63;
        Z[j*65 + i] = S[i*65 + j] * invf;
    }
    __syncthreads();

    for (int it = 0; it < 6; it++) {
        mm64_nn(T1, 65, S, 65, Z, 65, tid);
        __syncthreads();
        mm64_nn(T2, 65, Z, 65, T1, 65, tid);
        __syncthreads();
        for (int e = tid; e < 4096; e += 256) {
            int i = e >> 6, j = e & 63;
            Z[i*65 + j] = 2.f * Z[i*65 + j] - T2[i*65 + j];
        }
        __syncthreads();
    }

    for (int e = tid; e < 4096; e += 256) {
        int i = e >> 6, j = e & 63;
        gW2inv[bh*4096 + i*64 + j] = Z[i*65 + j];
    }
}

// ---------------- kernel_3 flash: softmax(q_lm k^T) @ v, partials ------------
__global__ void __launch_bounds__(256) k3_flash()
{
    extern __shared__ float sm3[];
    float* sQ  = sm3;           // 64*64
    float* sK  = sQ + 4096;     // 64*65
    float* sV  = sK + 4160;     // 64*64
    float* sS  = sV + 4096;     // 64*65
    float* m_s = sS + 4160;     // 64
    float* s_s = m_s + 64;
    float* c_s = s_s + 64;

    const int bh = blockIdx.x;
    const int ch = blockIdx.y;
    const int b = bh >> 3, h = bh & 7;
    const int tid = threadIdx.x;
    const int i0 = (tid >> 4) * 4, d0 = (tid & 15) * 4;

    for (int e = tid; e < 4096; e += 256) {
        int l = e >> 6, d = e & 63;
        sQ[l*64 + d] = gY[(size_t)(b * SEQ + l * LMSTRIDE) * QKV_N + h * HD + d];
    }
    if (tid < 64) { m_s[tid] = -1e30f; s_s[tid] = 0.f; }
    float acc[4][4] = {};
    __syncthreads();

    for (int t = 0; t < TILES_PER_CH; t++) {
        int n0 = ch * KEYS_PER_CH + t * 64;
        for (int e = tid; e < 4096; e += 256) {
            int j = e >> 6, d = e & 63;
            size_t base = (size_t)(b * SEQ + n0 + j) * QKV_N + h * HD + d;
            sK[j*65 + d] = gY[base + CDIM];
            sV[j*64 + d] = gY[base + 2*CDIM];
        }
        __syncthreads();
        mm64_nt(sS, 65, sQ, 64, sK, 65, SCALE, tid);
        __syncthreads();
        if (tid < 64) {
            float tmax = -1e30f;
            for (int j = 0; j < 64; j++) tmax = fmaxf(tmax, sS[tid*65 + j]);
            float mnew = fmaxf(m_s[tid], tmax);
            float corr = __expf(m_s[tid] - mnew);
            float rsum = 0.f;
            for (int j = 0; j < 64; j++) {
                float p = __expf(sS[tid*65 + j] - mnew);
                sS[tid*65 + j] = p;
                rsum += p;
            }
            s_s[tid] = s_s[tid] * corr + rsum;
            c_s[tid] = corr;
            m_s[tid] = mnew;
        }
        __syncthreads();
        #pragma unroll
        for (int ii = 0; ii < 4; ii++) {
            int l = i0 + ii;
            float corr = c_s[l];
            float r0 = acc[ii][0]*corr, r1 = acc[ii][1]*corr,
                  r2 = acc[ii][2]*corr, r3 = acc[ii][3]*corr;
            #pragma unroll 8
            for (int j = 0; j < 64; j++) {
                float p = sS[l*65 + j];
                float4 v = *(const float4*)&sV[j*64 + d0];
                r0 += p*v.x; r1 += p*v.y; r2 += p*v.z; r3 += p*v.w;
            }
            acc[ii][0]=r0; acc[ii][1]=r1; acc[ii][2]=r2; acc[ii][3]=r3;
        }
        __syncthreads();
    }

    size_t base = ((size_t)bh * NCH + ch) * 4096;
    #pragma unroll
    for (int ii = 0; ii < 4; ii++)
        *(float4*)&gFp[base + (size_t)(i0+ii)*64 + d0] =
            make_float4(acc[ii][0], acc[ii][1], acc[ii][2], acc[ii][3]);
    if (tid < 64) {
        gMp[(bh*NCH + ch)*64 + tid] = m_s[tid];
        gSp[(bh*NCH + ch)*64 + tid] = s_s[tid];
    }
}

// ---------------- combine flash partials + T = W2inv @ F --------------------
__global__ void __launch_bounds__(256) k3_combine()
{
    __shared__ float wgt[NCH*64];
    __shared__ float sF[64*65];
    __shared__ float sW[64*64];
    const int bh = blockIdx.x;
    const int tid = threadIdx.x;

    if (tid < 64) {
        float M = -1e30f;
        for (int c = 0; c < NCH; c++) M = fmaxf(M, gMp[(bh*NCH + c)*64 + tid]);
        float denom = 0.f;
        for (int c = 0; c < NCH; c++)
            denom += __expf(gMp[(bh*NCH + c)*64 + tid] - M) * gSp[(bh*NCH + c)*64 + tid];
        float invd = 1.f / denom;
        for (int c = 0; c < NCH; c++)
            wgt[c*64 + tid] = __expf(gMp[(bh*NCH + c)*64 + tid] - M) * invd;
    }
    for (int e = tid; e < 4096; e += 256) sW[e] = gW2inv[bh*4096 + e];
    __syncthreads();

    for (int e = tid; e < 4096; e += 256) {
        int l = e >> 6, d = e & 63;
        float f = 0.f;
        for (int c = 0; c < NCH; c++)
            f += gFp[((size_t)bh * NCH + c) * 4096 + e] * wgt[c*64 + l];
        sF[l*65 + d] = f;
    }
    __syncthreads();

    const int i0 = (tid >> 4) * 4, j0 = (tid & 15) * 4;
    float c[4][4] = {};
    #pragma unroll 8
    for (int k = 0; k < 64; k++) {
        float a[4], bv[4];
        #pragma unroll
        for (int ii = 0; ii < 4; ii++) a[ii] = sW[(i0+ii)*64 + k];
        #pragma unroll
        for (int jj = 0; jj < 4; jj++) bv[jj] = sF[k*65 + j0+jj];
        #pragma unroll
        for (int ii = 0; ii < 4; ii++)
            #pragma unroll
            for (int jj = 0; jj < 4; jj++)
                c[ii][jj] += a[ii] * bv[jj];
    }
    #pragma unroll
    for (int ii = 0; ii < 4; ii++)
        #pragma unroll
        for (int jj = 0; jj < 4; jj++)
            gT[bh*4096 + (i0+ii)*64 + j0+jj] = c[ii][jj];
}

// ---------------- kernel_1 @ T -> attention output ---------------------------
__global__ void __launch_bounds__(256) k4_out()
{
    extern __shared__ float sm4[];
    float* sK = sm4;            // 64*65 k_lm
    float* sT = sK + 4160;      // 64*64
    float* sQ = sT + 4096;      // 64*64
    float* sS = sQ + 4096;      // 64*65

    const int bh = blockIdx.y;
    const int qt = blockIdx.x;
    const int b = bh >> 3, h = bh & 7;
    const int n0 = qt * 64;
    const int tid = threadIdx.x;

    for (int e = tid; e < 4096; e += 256) {
        int l = e >> 6, d = e & 63;
        sK[l*65 + d] = gY[(size_t)(b * SEQ + l * LMSTRIDE) * QKV_N + CDIM + h * HD + d];
        sT[l*64 + d] = gT[bh*4096 + e];
        sQ[l*64 + d] = gY[(size_t)(b * SEQ + n0 + l) * QKV_N + h * HD + d];
    }
    __syncthreads();

    mm64_nt(sS, 65, sQ, 64, sK, 65, SCALE, tid);
    __syncthreads();
    if (tid < 64) {
        float mx = -1e30f;
        for (int j = 0; j < 64; j++) mx = fmaxf(mx, sS[tid*65 + j]);
        float s = 0.f;
        for (int j = 0; j < 64; j++) { float p = __expf(sS[tid*65+j] - mx); sS[tid*65+j] = p; s += p; }
        float inv = 1.f / s;
        for (int j = 0; j < 64; j++) sS[tid*65 + j] *= inv;
    }
    __syncthreads();

    const int i0 = (tid >> 4) * 4, d0 = (tid & 15) * 4;
    float c[4][4] = {};
    #pragma unroll 8
    for (int l = 0; l < 64; l++) {
        float a[4];
        #pragma unroll
        for (int ii = 0; ii < 4; ii++) a[ii] = sS[(i0+ii)*65 + l];
        float4 tv = *(const float4*)&sT[l*64 + d0];
        #pragma unroll
        for (int ii = 0; ii < 4; ii++) {
            c[ii][0] += a[ii]*tv.x; c[ii][1] += a[ii]*tv.y;
            c[ii][2] += a[ii]*tv.z; c[ii][3] += a[ii]*tv.w;
        }
    }
    #pragma unroll
    for (int ii = 0; ii < 4; ii++)
        *(float4*)&gAT[(size_t)(b * SEQ + n0 + i0 + ii) * CDIM + h * HD + d0] =
            make_float4(c[ii][0], c[ii][1], c[ii][2], c[ii][3]);
}

// ---------------- launcher ---------------------------------------------------
extern "C" void kernel_launch(void* const* d_in, const int* in_sizes, int n_in,
                              void* d_out, int out_size)
{
    const float* x     = (const float*)d_in[0];
    const float* Wqkv  = (const float*)d_in[1];
    const float* bqkv  = (const float*)d_in[2];
    const float* Wproj = (const float*)d_in[3];
    const float* bproj = (const float*)d_in[4];
    float* out = (float*)d_out;

    const int SMEM_K2 = 4 * 4160 * 4;                              // 66560
    const int SMEM_K3 = (4096 + 4160 + 4096 + 4160 + 192) * 4;     // 66816
    const int SMEM_K4 = (4160 + 4096 + 4096 + 4160) * 4;           // 66048
    cudaFuncSetAttribute(k2_newton, cudaFuncAttributeMaxDynamicSharedMemorySize, SMEM_K2);
    cudaFuncSetAttribute(k3_flash,  cudaFuncAttributeMaxDynamicSharedMemorySize, SMEM_K3);
    cudaFuncSetAttribute(k4_out,    cudaFuncAttributeMaxDynamicSharedMemorySize, SMEM_K4);

    float *pY, *pAT;
    cudaGetSymbolAddress((void**)&pY,  gY);
    cudaGetSymbolAddress((void**)&pAT, gAT);

    // 1. QKV projection: gY = x @ Wqkv^T + bqkv   (tensor cores, tf32)
    gemm_tf32<<<dim3(QKV_N/128, BN_TOK/128), 256>>>(x, Wqkv, bqkv, pY, BN_TOK, QKV_N, CDIM);
    // 2. kernel_2 softmax + Newton inverse
    k2_newton<<<NBH, 256, SMEM_K2>>>();
    // 3. kernel_3 flash softmax @ v (partials), then combine + T = W2inv @ F
    k3_flash<<<dim3(NBH, NCH), 256, SMEM_K3>>>();
    k3_combine<<<NBH, 256>>>();
    // 4. out = softmax(q k_lm^T) @ T  -> gAT in [B,N,C] layout
    k4_out<<<dim3(SEQ/64, NBH), 256, SMEM_K4>>>();
    // 5. projection: out = gAT @ Wproj^T + bproj  (tensor cores, tf32)
    gemm_tf32<<<dim3(CDIM/128, BN_TOK/128), 256>>>(pAT, Wproj, bproj, out, BN_TOK, CDIM, CDIM);
}

// round 4
// speedup vs baseline: 2.0203x; 1.1217x over previous
#include <cuda_runtime.h>
#include <cuda_fp16.h>
#include <cstdint>

// ---------------- problem constants ----------------
#define BDIM     4
#define SEQ      8192
#define CDIM     512
#define NH       8
#define HD       64
#define NLM      64
#define LMSTRIDE 128           // SEQ / NLM
#define BN_TOK   (BDIM*SEQ)    // 32768
#define QKV_N    (3*CDIM)      // 1536
#define NBH      (BDIM*NH)     // 32
#define NCH      32            // key chunks for kernel_3 flash
#define KEYS_PER_CH (SEQ/NCH)  // 256
#define TILES_PER_CH (KEYS_PER_CH/64) // 4
#define SCALE    0.125f        // hd^-0.5

// ---------------- device scratch (no runtime allocs allowed) ----------------
__device__ float gY [(size_t)BN_TOK * QKV_N];   // qkv activations, [B*N,1536]
__device__ float gAT[(size_t)BN_TOK * CDIM];    // attention output, [B*N,512]
__device__ float gW2inv[NBH*64*64];
__device__ float gT    [NBH*64*64];             // W2inv @ F
__device__ float gFp[(size_t)NBH*NCH*64*64];    // flash partial accumulators
__device__ float gMp[NBH*NCH*64];
__device__ float gSp[NBH*NCH*64];

// ---------------- fp16 helpers ----------------------------------------------
__device__ __forceinline__ void mma_f16(float* d, const uint32_t* a, const uint32_t* b) {
    asm volatile(
        "mma.sync.aligned.m16n8k16.row.col.f32.f16.f16.f32 "
        "{%0,%1,%2,%3}, {%4,%5,%6,%7}, {%8,%9}, {%0,%1,%2,%3};"
        : "+f"(d[0]), "+f"(d[1]), "+f"(d[2]), "+f"(d[3])
        : "r"(a[0]), "r"(a[1]), "r"(a[2]), "r"(a[3]),
          "r"(b[0]), "r"(b[1]));
}

// store 8 floats as 8 halves (4 half2 words) to smem
__device__ __forceinline__ void sts_h8(uint32_t addr, float4 u, float4 v) {
    __half2 h0 = __floats2half2_rn(u.x, u.y);
    __half2 h1 = __floats2half2_rn(u.z, u.w);
    __half2 h2 = __floats2half2_rn(v.x, v.y);
    __half2 h3 = __floats2half2_rn(v.z, v.w);
    asm volatile("st.shared.v4.b32 [%0], {%1, %2, %3, %4};"
                 :: "r"(addr),
                    "r"(*(uint32_t*)&h0), "r"(*(uint32_t*)&h1),
                    "r"(*(uint32_t*)&h2), "r"(*(uint32_t*)&h3) : "memory");
}

__device__ __forceinline__ uint32_t smem_u32(const void* p) {
    uint32_t a;
    asm("{ .reg .u64 t; cvta.to.shared.u64 t, %1; cvt.u32.u64 %0, t; }" : "=r"(a) : "l"(p));
    return a;
}

// ---------------- fp16 tensor-core GEMM: C = A[M,K] @ B[N,K]^T + bias -------
// block 128x128, 256 threads (8 warps of 64x32), K chunk 32, double-buffered.
// smem rows: 32 halves data + 8 halves pad = 20 b32 words per row.
#define LDSW 20  // b32 words per smem row

__global__ void __launch_bounds__(256) gemm_f16(const float* __restrict__ A,
                                                const float* __restrict__ B,
                                                const float* __restrict__ bias,
                                                float* __restrict__ C,
                                                int M, int N, int K)
{
    __shared__ uint32_t As[2][128 * LDSW];
    __shared__ uint32_t Bs[2][128 * LDSW];

    const int bm = blockIdx.y * 128;
    const int bn = blockIdx.x * 128;
    const int tid  = threadIdx.x;
    const int lane = tid & 31;
    const int warp = tid >> 5;
    const int wm = (warp & 1) * 64;   // warp M offset
    const int wn = (warp >> 1) * 32;  // warp N offset
    const int g = lane >> 2;          // groupID 0..7
    const int c = lane & 3;           // thread-in-group 0..3

    // staging map: row r0 (and r0+64), 8-float chunk q within the 32-float K chunk
    const int r0 = tid >> 2;          // 0..63
    const int q  = tid & 3;           // 0..3

    const uint32_t as_base = smem_u32(As);
    const uint32_t bs_base = smem_u32(Bs);

    float acc[4][4][4];
    #pragma unroll
    for (int mi = 0; mi < 4; mi++)
        #pragma unroll
        for (int ni = 0; ni < 4; ni++)
            #pragma unroll
            for (int r = 0; r < 4; r++) acc[mi][ni][r] = 0.f;

    const float* Ap = A + (size_t)(bm + r0) * K + q * 8;
    const float* Bp = B + (size_t)(bn + r0) * K + q * 8;
    const size_t row64 = (size_t)64 * K;

    float4 va[2][2], vb[2][2];
    // prologue: chunk 0
    #pragma unroll
    for (int j = 0; j < 2; j++) {
        va[j][0] = *(const float4*)(Ap + j * row64);
        va[j][1] = *(const float4*)(Ap + j * row64 + 4);
        vb[j][0] = *(const float4*)(Bp + j * row64);
        vb[j][1] = *(const float4*)(Bp + j * row64 + 4);
    }
    {
        #pragma unroll
        for (int j = 0; j < 2; j++) {
            uint32_t wo = (uint32_t)(r0 + j * 64) * LDSW + q * 4;
            sts_h8(as_base + wo * 4, va[j][0], va[j][1]);
            sts_h8(bs_base + wo * 4, vb[j][0], vb[j][1]);
        }
    }

    const int KT = K >> 5;  // K/32
    for (int kt = 0; kt < KT; kt++) {
        __syncthreads();

        const bool more = (kt + 1 < KT);
        if (more) {
            const int k0 = (kt + 1) * 32;
            #pragma unroll
            for (int j = 0; j < 2; j++) {
                va[j][0] = *(const float4*)(Ap + j * row64 + k0);
                va[j][1] = *(const float4*)(Ap + j * row64 + k0 + 4);
                vb[j][0] = *(const float4*)(Bp + j * row64 + k0);
                vb[j][1] = *(const float4*)(Bp + j * row64 + k0 + 4);
            }
        }

        const int buf = kt & 1;
        const uint32_t* as = As[buf];
        const uint32_t* bs = Bs[buf];

        #pragma unroll
        for (int ks = 0; ks < 2; ks++) {
            const int kb = ks * 8;  // word offset of this k-step
            uint32_t af[4][4], bf[4][2];
            #pragma unroll
            for (int mi = 0; mi < 4; mi++) {
                const int row = wm + mi * 16 + g;
                af[mi][0] = as[row * LDSW + kb + c];
                af[mi][1] = as[(row + 8) * LDSW + kb + c];
                af[mi][2] = as[row * LDSW + kb + c + 4];
                af[mi][3] = as[(row + 8) * LDSW + kb + c + 4];
            }
            #pragma unroll
            for (int ni = 0; ni < 4; ni++) {
                const int col = wn + ni * 8 + g;
                bf[ni][0] = bs[col * LDSW + kb + c];
                bf[ni][1] = bs[col * LDSW + kb + c + 4];
            }
            #pragma unroll
            for (int mi = 0; mi < 4; mi++)
                #pragma unroll
                for (int ni = 0; ni < 4; ni++)
                    mma_f16(acc[mi][ni], af[mi], bf[ni]);
        }

        if (more) {
            __syncthreads();
            const int nbuf = buf ^ 1;
            const uint32_t ab = as_base + (uint32_t)nbuf * (128 * LDSW * 4);
            const uint32_t bb = bs_base + (uint32_t)nbuf * (128 * LDSW * 4);
            #pragma unroll
            for (int j = 0; j < 2; j++) {
                uint32_t wo = (uint32_t)(r0 + j * 64) * LDSW + q * 4;
                sts_h8(ab + wo * 4, va[j][0], va[j][1]);
                sts_h8(bb + wo * 4, vb[j][0], vb[j][1]);
            }
        }
    }

    // epilogue: C[row, col] = acc + bias[col]
    #pragma unroll
    for (int mi = 0; mi < 4; mi++) {
        const int row = bm + wm + mi * 16 + g;
        #pragma unroll
        for (int ni = 0; ni < 4; ni++) {
            const int col = bn + wn + ni * 8 + 2 * c;
            const float b0 = bias[col], b1 = bias[col + 1];
            float2 o0 = make_float2(acc[mi][ni][0] + b0, acc[mi][ni][1] + b1);
            float2 o1 = make_float2(acc[mi][ni][2] + b0, acc[mi][ni][3] + b1);
            *(float2*)(C + (size_t)row * N + col)       = o0;
            *(float2*)(C + (size_t)(row + 8) * N + col) = o1;
        }
    }
}

// ---------------- small 64x64 matmul helpers (4x4 register tiles) -----------
__device__ __forceinline__ void mm64_nt(float* C, int ldc,
                                        const float* A, int lda,
                                        const float* B, int ldb,
                                        float scale, int tid)
{
    const int i0 = (tid >> 4) * 4, j0 = (tid & 15) * 4;
    float c[4][4] = {};
    #pragma unroll 8
    for (int d = 0; d < 64; d++) {
        float a[4], bv[4];
        #pragma unroll
        for (int ii = 0; ii < 4; ii++) a[ii]  = A[(i0+ii)*lda + d];
        #pragma unroll
        for (int jj = 0; jj < 4; jj++) bv[jj] = B[(j0+jj)*ldb + d];
        #pragma unroll
        for (int ii = 0; ii < 4; ii++)
            #pragma unroll
            for (int jj = 0; jj < 4; jj++)
                c[ii][jj] += a[ii] * bv[jj];
    }
    #pragma unroll
    for (int ii = 0; ii < 4; ii++)
        #pragma unroll
        for (int jj = 0; jj < 4; jj++)
            C[(i0+ii)*ldc + j0+jj] = scale * c[ii][jj];
}

__device__ __forceinline__ void mm64_nn(float* C, int ldc,
                                        const float* A, int lda,
                                        const float* B, int ldb, int tid)
{
    const int i0 = (tid >> 4) * 4, j0 = (tid & 15) * 4;
    float c[4][4] = {};
    #pragma unroll 8
    for (int k = 0; k < 64; k++) {
        float a[4], bv[4];
        #pragma unroll
        for (int ii = 0; ii < 4; ii++) a[ii]  = A[(i0+ii)*lda + k];
        #pragma unroll
        for (int jj = 0; jj < 4; jj++) bv[jj] = B[k*ldb + j0+jj];
        #pragma unroll
        for (int ii = 0; ii < 4; ii++)
            #pragma unroll
            for (int jj = 0; jj < 4; jj++)
                c[ii][jj] += a[ii] * bv[jj];
    }
    #pragma unroll
    for (int ii = 0; ii < 4; ii++)
        #pragma unroll
        for (int jj = 0; jj < 4; jj++)
            C[(i0+ii)*ldc + j0+jj] = c[ii][jj];
}

// ---------------- kernel_2 softmax + Newton pseudo-inverse -------------------
__global__ void __launch_bounds__(256) k2_newton()
{
    extern __shared__ float sm2[];
    float* S  = sm2;
    float* Z  = S  + 4160;
    float* T1 = Z  + 4160;
    float* T2 = T1 + 4160;
    __shared__ float red[8];

    const int bh = blockIdx.x;
    const int b = bh >> 3, h = bh & 7;
    const int tid = threadIdx.x;

    for (int e = tid; e < 4096; e += 256) {
        int l = e >> 6, d = e & 63;
        size_t base = (size_t)(b * SEQ + l * LMSTRIDE) * QKV_N + h * HD + d;
        Z [l*65 + d] = gY[base];
        T1[l*65 + d] = gY[base + CDIM];
    }
    __syncthreads();

    mm64_nt(S, 65, Z, 65, T1, 65, SCALE, tid);
    __syncthreads();
    if (tid < 64) {
        float mx = -1e30f;
        for (int j = 0; j < 64; j++) mx = fmaxf(mx, S[tid*65 + j]);
        float s = 0.f;
        for (int j = 0; j < 64; j++) { float p = __expf(S[tid*65+j] - mx); S[tid*65+j] = p; s += p; }
        float inv = 1.f / s;
        for (int j = 0; j < 64; j++) S[tid*65 + j] *= inv;
    }
    __syncthreads();

    float part = 0.f;
    for (int e = tid; e < 4096; e += 256) {
        int i = e >> 6, j = e & 63;
        float v = S[i*65 + j];
        part += v * v;
    }
    #pragma unroll
    for (int o = 16; o; o >>= 1) part += __shfl_xor_sync(0xffffffffu, part, o);
    if ((tid & 31) == 0) red[tid >> 5] = part;
    __syncthreads();
    float fro2 = red[0]+red[1]+red[2]+red[3]+red[4]+red[5]+red[6]+red[7];
    fro2 = fmaxf(fro2, 1e-12f);
    float invf = 1.f / fro2;

    for (int e = tid; e < 4096; e += 256) {
        int i = e >> 6, j = e & 63;
        Z[j*65 + i] = S[i*65 + j] * invf;
    }
    __syncthreads();

    for (int it = 0; it < 6; it++) {
        mm64_nn(T1, 65, S, 65, Z, 65, tid);
        __syncthreads();
        mm64_nn(T2, 65, Z, 65, T1, 65, tid);
        __syncthreads();
        for (int e = tid; e < 4096; e += 256) {
            int i = e >> 6, j = e & 63;
            Z[i*65 + j] = 2.f * Z[i*65 + j] - T2[i*65 + j];
        }
        __syncthreads();
    }

    for (int e = tid; e < 4096; e += 256) {
        int i = e >> 6, j = e & 63;
        gW2inv[bh*4096 + i*64 + j] = Z[i*65 + j];
    }
}

// ---------------- kernel_3 flash: softmax(q_lm k^T) @ v, partials ------------
__global__ void __launch_bounds__(256) k3_flash()
{
    extern __shared__ float sm3[];
    float* sQ  = sm3;           // 64*64
    float* sK  = sQ + 4096;     // 64*65
    float* sV  = sK + 4160;     // 64*64
    float* sS  = sV + 4096;     // 64*65
    float* m_s = sS + 4160;     // 64
    float* s_s = m_s + 64;
    float* c_s = s_s + 64;

    const int bh = blockIdx.x;
    const int ch = blockIdx.y;
    const int b = bh >> 3, h = bh & 7;
    const int tid = threadIdx.x;
    const int i0 = (tid >> 4) * 4, d0 = (tid & 15) * 4;

    for (int e = tid; e < 4096; e += 256) {
        int l = e >> 6, d = e & 63;
        sQ[l*64 + d] = gY[(size_t)(b * SEQ + l * LMSTRIDE) * QKV_N + h * HD + d];
    }
    if (tid < 64) { m_s[tid] = -1e30f; s_s[tid] = 0.f; }
    float acc[4][4] = {};
    __syncthreads();

    for (int t = 0; t < TILES_PER_CH; t++) {
        int n0 = ch * KEYS_PER_CH + t * 64;
        for (int e = tid; e < 4096; e += 256) {
            int j = e >> 6, d = e & 63;
            size_t base = (size_t)(b * SEQ + n0 + j) * QKV_N + h * HD + d;
            sK[j*65 + d] = gY[base + CDIM];
            sV[j*64 + d] = gY[base + 2*CDIM];
        }
        __syncthreads();
        mm64_nt(sS, 65, sQ, 64, sK, 65, SCALE, tid);
        __syncthreads();
        if (tid < 64) {
            float tmax = -1e30f;
            for (int j = 0; j < 64; j++) tmax = fmaxf(tmax, sS[tid*65 + j]);
            float mnew = fmaxf(m_s[tid], tmax);
            float corr = __expf(m_s[tid] - mnew);
            float rsum = 0.f;
            for (int j = 0; j < 64; j++) {
                float p = __expf(sS[tid*65 + j] - mnew);
                sS[tid*65 + j] = p;
                rsum += p;
            }
            s_s[tid] = s_s[tid] * corr + rsum;
            c_s[tid] = corr;
            m_s[tid] = mnew;
        }
        __syncthreads();
        #pragma unroll
        for (int ii = 0; ii < 4; ii++) {
            int l = i0 + ii;
            float corr = c_s[l];
            float r0 = acc[ii][0]*corr, r1 = acc[ii][1]*corr,
                  r2 = acc[ii][2]*corr, r3 = acc[ii][3]*corr;
            #pragma unroll 8
            for (int j = 0; j < 64; j++) {
                float p = sS[l*65 + j];
                float4 v = *(const float4*)&sV[j*64 + d0];
                r0 += p*v.x; r1 += p*v.y; r2 += p*v.z; r3 += p*v.w;
            }
            acc[ii][0]=r0; acc[ii][1]=r1; acc[ii][2]=r2; acc[ii][3]=r3;
        }
        __syncthreads();
    }

    size_t base = ((size_t)bh * NCH + ch) * 4096;
    #pragma unroll
    for (int ii = 0; ii < 4; ii++)
        *(float4*)&gFp[base + (size_t)(i0+ii)*64 + d0] =
            make_float4(acc[ii][0], acc[ii][1], acc[ii][2], acc[ii][3]);
    if (tid < 64) {
        gMp[(bh*NCH + ch)*64 + tid] = m_s[tid];
        gSp[(bh*NCH + ch)*64 + tid] = s_s[tid];
    }
}

// ---------------- combine flash partials + T = W2inv @ F --------------------
__global__ void __launch_bounds__(256) k3_combine()
{
    __shared__ float wgt[NCH*64];
    __shared__ float sF[64*65];
    __shared__ float sW[64*64];
    const int bh = blockIdx.x;
    const int tid = threadIdx.x;

    if (tid < 64) {
        float M = -1e30f;
        for (int c = 0; c < NCH; c++) M = fmaxf(M, gMp[(bh*NCH + c)*64 + tid]);
        float denom = 0.f;
        for (int c = 0; c < NCH; c++)
            denom += __expf(gMp[(bh*NCH + c)*64 + tid] - M) * gSp[(bh*NCH + c)*64 + tid];
        float invd = 1.f / denom;
        for (int c = 0; c < NCH; c++)
            wgt[c*64 + tid] = __expf(gMp[(bh*NCH + c)*64 + tid] - M) * invd;
    }
    for (int e = tid; e < 4096; e += 256) sW[e] = gW2inv[bh*4096 + e];
    __syncthreads();

    for (int e = tid; e < 4096; e += 256) {
        int l = e >> 6, d = e & 63;
        float f = 0.f;
        for (int c = 0; c < NCH; c++)
            f += gFp[((size_t)bh * NCH + c) * 4096 + e] * wgt[c*64 + l];
        sF[l*65 + d] = f;
    }
    __syncthreads();

    const int i0 = (tid >> 4) * 4, j0 = (tid & 15) * 4;
    float c[4][4] = {};
    #pragma unroll 8
    for (int k = 0; k < 64; k++) {
        float a[4], bv[4];
        #pragma unroll
        for (int ii = 0; ii < 4; ii++) a[ii] = sW[(i0+ii)*64 + k];
        #pragma unroll
        for (int jj = 0; jj < 4; jj++) bv[jj] = sF[k*65 + j0+jj];
        #pragma unroll
        for (int ii = 0; ii < 4; ii++)
            #pragma unroll
            for (int jj = 0; jj < 4; jj++)
                c[ii][jj] += a[ii] * bv[jj];
    }
    #pragma unroll
    for (int ii = 0; ii < 4; ii++)
        #pragma unroll
        for (int jj = 0; jj < 4; jj++)
            gT[bh*4096 + (i0+ii)*64 + j0+jj] = c[ii][jj];
}

// ---------------- kernel_1 @ T -> attention output ---------------------------
__global__ void __launch_bounds__(256) k4_out()
{
    extern __shared__ float sm4[];
    float* sK = sm4;            // 64*65 k_lm
    float* sT = sK + 4160;      // 64*64
    float* sQ = sT + 4096;      // 64*64
    float* sS = sQ + 4096;      // 64*65

    const int bh = blockIdx.y;
    const int qt = blockIdx.x;
    const int b = bh >> 3, h = bh & 7;
    const int n0 = qt * 64;
    const int tid = threadIdx.x;

    for (int e = tid; e < 4096; e += 256) {
        int l = e >> 6, d = e & 63;
        sK[l*65 + d] = gY[(size_t)(b * SEQ + l * LMSTRIDE) * QKV_N + CDIM + h * HD + d];
        sT[l*64 + d] = gT[bh*4096 + e];
        sQ[l*64 + d] = gY[(size_t)(b * SEQ + n0 + l) * QKV_N + h * HD + d];
    }
    __syncthreads();

    mm64_nt(sS, 65, sQ, 64, sK, 65, SCALE, tid);
    __syncthreads();
    if (tid < 64) {
        float mx = -1e30f;
        for (int j = 0; j < 64; j++) mx = fmaxf(mx, sS[tid*65 + j]);
        float s = 0.f;
        for (int j = 0; j < 64; j++) { float p = __expf(sS[tid*65+j] - mx); sS[tid*65+j] = p; s += p; }
        float inv = 1.f / s;
        for (int j = 0; j < 64; j++) sS[tid*65 + j] *= inv;
    }
    __syncthreads();

    const int i0 = (tid >> 4) * 4, d0 = (tid & 15) * 4;
    float c[4][4] = {};
    #pragma unroll 8
    for (int l = 0; l < 64; l++) {
        float a[4];
        #pragma unroll
        for (int ii = 0; ii < 4; ii++) a[ii] = sS[(i0+ii)*65 + l];
        float4 tv = *(const float4*)&sT[l*64 + d0];
        #pragma unroll
        for (int ii = 0; ii < 4; ii++) {
            c[ii][0] += a[ii]*tv.x; c[ii][1] += a[ii]*tv.y;
            c[ii][2] += a[ii]*tv.z; c[ii][3] += a[ii]*tv.w;
        }
    }
    #pragma unroll
    for (int ii = 0; ii < 4; ii++)
        *(float4*)&gAT[(size_t)(b * SEQ + n0 + i0 + ii) * CDIM + h * HD + d0] =
            make_float4(c[ii][0], c[ii][1], c[ii][2], c[ii][3]);
}

// ---------------- launcher ---------------------------------------------------
extern "C" void kernel_launch(void* const* d_in, const int* in_sizes, int n_in,
                              void* d_out, int out_size)
{
    const float* x     = (const float*)d_in[0];
    const float* Wqkv  = (const float*)d_in[1];
    const float* bqkv  = (const float*)d_in[2];
    const float* Wproj = (const float*)d_in[3];
    const float* bproj = (const float*)d_in[4];
    float* out = (float*)d_out;

    const int SMEM_K2 = 4 * 4160 * 4;                              // 66560
    const int SMEM_K3 = (4096 + 4160 + 4096 + 4160 + 192) * 4;     // 66816
    const int SMEM_K4 = (4160 + 4096 + 4096 + 4160) * 4;           // 66048
    cudaFuncSetAttribute(k2_newton, cudaFuncAttributeMaxDynamicSharedMemorySize, SMEM_K2);
    cudaFuncSetAttribute(k3_flash,  cudaFuncAttributeMaxDynamicSharedMemorySize, SMEM_K3);
    cudaFuncSetAttribute(k4_out,    cudaFuncAttributeMaxDynamicSharedMemorySize, SMEM_K4);

    float *pY, *pAT;
    cudaGetSymbolAddress((void**)&pY,  gY);
    cudaGetSymbolAddress((void**)&pAT, gAT);

    // 1. QKV projection: gY = x @ Wqkv^T + bqkv   (fp16 tensor cores)
    gemm_f16<<<dim3(QKV_N/128, BN_TOK/128), 256>>>(x, Wqkv, bqkv, pY, BN_TOK, QKV_N, CDIM);
    // 2. kernel_2 softmax + Newton inverse
    k2_newton<<<NBH, 256, SMEM_K2>>>();
    // 3. kernel_3 flash softmax @ v (partials), then combine + T = W2inv @ F
    k3_flash<<<dim3(NBH, NCH), 256, SMEM_K3>>>();
    k3_combine<<<NBH, 256>>>();
    // 4. out = softmax(q k_lm^T) @ T  -> gAT in [B,N,C] layout
    k4_out<<<dim3(SEQ/64, NBH), 256, SMEM_K4>>>();
    // 5. projection: out = gAT @ Wproj^T + bproj  (fp16 tensor cores)
    gemm_f16<<<dim3(CDIM/128, BN_TOK/128), 256>>>(pAT, Wproj, bproj, out, BN_TOK, CDIM, CDIM);
}

// round 5
// speedup vs baseline: 2.7153x; 1.3440x over previous
#include <cuda_runtime.h>
#include <cuda_fp16.h>
#include <cstdint>

// ---------------- problem constants ----------------
#define BDIM     4
#define SEQ      8192
#define CDIM     512
#define NH       8
#define HD       64
#define NLM      64
#define LMSTRIDE 128           // SEQ / NLM
#define BN_TOK   (BDIM*SEQ)    // 32768
#define QKV_N    (3*CDIM)      // 1536
#define NBH      (BDIM*NH)     // 32
#define NCH      32            // key chunks for kernel_3 flash
#define KEYS_PER_CH (SEQ/NCH)  // 256
#define TILES_PER_CH (KEYS_PER_CH/64) // 4
#define SCALE    0.125f        // hd^-0.5

// ---------------- device scratch (no runtime allocs allowed) ----------------
__device__ float  gY [(size_t)BN_TOK * QKV_N];   // qkv activations, [B*N,1536] fp32
__device__ __half gXh[(size_t)BN_TOK * CDIM];    // x in fp16
__device__ __half gWqkvh[QKV_N * CDIM];          // Wqkv in fp16
__device__ __half gWph[CDIM * CDIM];             // Wproj in fp16
__device__ __half gATh[(size_t)BN_TOK * CDIM];   // attention output, fp16
__device__ float gW2inv[NBH*64*64];
__device__ float gT    [NBH*64*64];              // W2inv @ F
__device__ float gFp[(size_t)NBH*NCH*64*64];     // flash partial accumulators
__device__ float gMp[NBH*NCH*64];
__device__ float gSp[NBH*NCH*64];

// ---------------- ptx helpers ------------------------------------------------
__device__ __forceinline__ uint32_t smem_u32(const void* p) {
    uint32_t a;
    asm("{ .reg .u64 t; cvta.to.shared.u64 t, %1; cvt.u32.u64 %0, t; }" : "=r"(a) : "l"(p));
    return a;
}
__device__ __forceinline__ void mma_f16(float* d, const uint32_t* a, const uint32_t* b) {
    asm volatile(
        "mma.sync.aligned.m16n8k16.row.col.f32.f16.f16.f32 "
        "{%0,%1,%2,%3}, {%4,%5,%6,%7}, {%8,%9}, {%0,%1,%2,%3};"
        : "+f"(d[0]), "+f"(d[1]), "+f"(d[2]), "+f"(d[3])
        : "r"(a[0]), "r"(a[1]), "r"(a[2]), "r"(a[3]),
          "r"(b[0]), "r"(b[1]));
}
__device__ __forceinline__ void ldsm_x4(uint32_t* r, uint32_t addr) {
    asm volatile("ldmatrix.sync.aligned.m8n8.x4.shared.b16 {%0,%1,%2,%3}, [%4];"
                 : "=r"(r[0]), "=r"(r[1]), "=r"(r[2]), "=r"(r[3]) : "r"(addr));
}
#define CP_ASYNC16(dst, src) \
    asm volatile("cp.async.cg.shared.global [%0], [%1], 16;" :: "r"(dst), "l"(src) : "memory")
#define CP_COMMIT() asm volatile("cp.async.commit_group;" ::: "memory")
#define CP_WAIT1()  asm volatile("cp.async.wait_group 1;" ::: "memory")

// ---------------- fp32 -> fp16 conversion (grid-stride over 8-elem chunks) --
__global__ void __launch_bounds__(256) cvtf2h(const float* __restrict__ s,
                                              __half* __restrict__ d, int n)
{
    int i = (blockIdx.x * blockDim.x + threadIdx.x) * 8;
    if (i < n) {
        float4 a = *(const float4*)(s + i);
        float4 b = *(const float4*)(s + i + 4);
        __half2 h0 = __floats2half2_rn(a.x, a.y);
        __half2 h1 = __floats2half2_rn(a.z, a.w);
        __half2 h2 = __floats2half2_rn(b.x, b.y);
        __half2 h3 = __floats2half2_rn(b.z, b.w);
        uint4 o;
        o.x = *(uint32_t*)&h0; o.y = *(uint32_t*)&h1;
        o.z = *(uint32_t*)&h2; o.w = *(uint32_t*)&h3;
        *(uint4*)(d + i) = o;
    }
}

// ---------------- fp16 tensor-core GEMM: C = A[M,K]h @ B[N,K]h^T + bias -----
// block 128x128, 8 warps (warp 64x32), K chunk 64 halves (128B rows, XOR swizzle),
// 3-stage cp.async pipeline, ldmatrix.x4 fragment loads.
#define STG_BYTES 32768          // 16KB A + 16KB B per stage
#define SMEM_GEMMH (3 * STG_BYTES)

__device__ __forceinline__ void stage_copy(uint32_t sbase, const __half* A,
                                           const __half* B, int bm, int bn,
                                           int K, int k0, int tid)
{
    #pragma unroll
    for (int i = 0; i < 4; i++) {
        int lin = tid + i * 256;          // 0..1023
        int row = lin >> 3;               // 0..127
        int c   = lin & 7;                // 16B chunk within 128B row
        uint32_t dA = sbase + row * 128 + ((c ^ (row & 7)) << 4);
        CP_ASYNC16(dA, A + (size_t)(bm + row) * K + k0 + c * 8);
        uint32_t dB = sbase + 16384 + row * 128 + ((c ^ (row & 7)) << 4);
        CP_ASYNC16(dB, B + (size_t)(bn + row) * K + k0 + c * 8);
    }
}

__global__ void __launch_bounds__(256) gemm_h(const __half* __restrict__ A,
                                              const __half* __restrict__ B,
                                              const float* __restrict__ bias,
                                              float* __restrict__ C,
                                              int M, int N, int K)
{
    extern __shared__ __align__(128) char smg[];
    const uint32_t sb = smem_u32(smg);

    const int bm = blockIdx.y * 128;
    const int bn = blockIdx.x * 128;
    const int tid  = threadIdx.x;
    const int lane = tid & 31;
    const int warp = tid >> 5;
    const int wm = (warp & 1) * 64;
    const int wn = (warp >> 1) * 32;
    const int g = lane >> 2;
    const int c = lane & 3;
    const int lrow = lane & 15;       // ldmatrix row within 16-row group
    const int lhalf = lane >> 4;      // ldmatrix k-half select (0/1)

    float acc[4][4][4];
    #pragma unroll
    for (int mi = 0; mi < 4; mi++)
        #pragma unroll
        for (int t = 0; t < 4; t++)
            #pragma unroll
            for (int r = 0; r < 4; r++) acc[mi][t][r] = 0.f;

    const int KT = K >> 6;   // chunks of 64

    // prologue: stages 0 and 1
    stage_copy(sb, A, B, bm, bn, K, 0, tid);
    CP_COMMIT();
    stage_copy(sb + STG_BYTES, A, B, bm, bn, K, 64, tid);
    CP_COMMIT();

    for (int kt = 0; kt < KT; kt++) {
        CP_WAIT1();
        __syncthreads();

        if (kt + 2 < KT)
            stage_copy(sb + ((kt + 2) % 3) * STG_BYTES, A, B, bm, bn, K, (kt + 2) * 64, tid);
        CP_COMMIT();

        const uint32_t aBase = sb + (kt % 3) * STG_BYTES;
        const uint32_t bBase = aBase + 16384;

        #pragma unroll
        for (int ks = 0; ks < 4; ks++) {
            uint32_t af[4][4], bf[2][4];
            #pragma unroll
            for (int mi = 0; mi < 4; mi++) {
                const int row = wm + mi * 16 + lrow;
                const int ch  = (ks * 2 + lhalf) ^ (row & 7);
                ldsm_x4(af[mi], aBase + row * 128 + (ch << 4));
            }
            #pragma unroll
            for (int nj = 0; nj < 2; nj++) {
                const int row = wn + nj * 16 + lrow;
                const int ch  = (ks * 2 + lhalf) ^ (row & 7);
                ldsm_x4(bf[nj], bBase + row * 128 + (ch << 4));
            }
            #pragma unroll
            for (int mi = 0; mi < 4; mi++) {
                #pragma unroll
                for (int t = 0; t < 4; t++) {
                    const int nj = t >> 1, sub = t & 1;
                    uint32_t b2[2] = { bf[nj][sub], bf[nj][sub + 2] };
                    mma_f16(acc[mi][t], af[mi], b2);
                }
            }
        }
    }

    // epilogue: C[row, col] = acc + bias[col]
    #pragma unroll
    for (int mi = 0; mi < 4; mi++) {
        const int row = bm + wm + mi * 16 + g;
        #pragma unroll
        for (int t = 0; t < 4; t++) {
            const int col = bn + wn + (t >> 1) * 16 + (t & 1) * 8 + 2 * c;
            const float b0 = bias[col], b1 = bias[col + 1];
            float2 o0 = make_float2(acc[mi][t][0] + b0, acc[mi][t][1] + b1);
            float2 o1 = make_float2(acc[mi][t][2] + b0, acc[mi][t][3] + b1);
            *(float2*)(C + (size_t)row * N + col)       = o0;
            *(float2*)(C + (size_t)(row + 8) * N + col) = o1;
        }
    }
}

// ---------------- small 64x64 matmul helpers (4x4 register tiles) -----------
__device__ __forceinline__ void mm64_nt(float* C, int ldc,
                                        const float* A, int lda,
                                        const float* B, int ldb,
                                        float scale, int tid)
{
    const int i0 = (tid >> 4) * 4, j0 = (tid & 15) * 4;
    float c[4][4] = {};
    #pragma unroll 8
    for (int d = 0; d < 64; d++) {
        float a[4], bv[4];
        #pragma unroll
        for (int ii = 0; ii < 4; ii++) a[ii]  = A[(i0+ii)*lda + d];
        #pragma unroll
        for (int jj = 0; jj < 4; jj++) bv[jj] = B[(j0+jj)*ldb + d];
        #pragma unroll
        for (int ii = 0; ii < 4; ii++)
            #pragma unroll
            for (int jj = 0; jj < 4; jj++)
                c[ii][jj] += a[ii] * bv[jj];
    }
    #pragma unroll
    for (int ii = 0; ii < 4; ii++)
        #pragma unroll
        for (int jj = 0; jj < 4; jj++)
            C[(i0+ii)*ldc + j0+jj] = scale * c[ii][jj];
}

__device__ __forceinline__ void mm64_nn(float* C, int ldc,
                                        const float* A, int lda,
                                        const float* B, int ldb, int tid)
{
    const int i0 = (tid >> 4) * 4, j0 = (tid & 15) * 4;
    float c[4][4] = {};
    #pragma unroll 8
    for (int k = 0; k < 64; k++) {
        float a[4], bv[4];
        #pragma unroll
        for (int ii = 0; ii < 4; ii++) a[ii]  = A[(i0+ii)*lda + k];
        #pragma unroll
        for (int jj = 0; jj < 4; jj++) bv[jj] = B[k*ldb + j0+jj];
        #pragma unroll
        for (int ii = 0; ii < 4; ii++)
            #pragma unroll
            for (int jj = 0; jj < 4; jj++)
                c[ii][jj] += a[ii] * bv[jj];
    }
    #pragma unroll
    for (int ii = 0; ii < 4; ii++)
        #pragma unroll
        for (int jj = 0; jj < 4; jj++)
            C[(i0+ii)*ldc + j0+jj] = c[ii][jj];
}

// ---------------- kernel_2 softmax + Newton pseudo-inverse -------------------
__global__ void __launch_bounds__(256) k2_newton()
{
    extern __shared__ float sm2[];
    float* S  = sm2;
    float* Z  = S  + 4160;
    float* T1 = Z  + 4160;
    float* T2 = T1 + 4160;
    __shared__ float red[8];

    const int bh = blockIdx.x;
    const int b = bh >> 3, h = bh & 7;
    const int tid = threadIdx.x;

    for (int e = tid; e < 4096; e += 256) {
        int l = e >> 6, d = e & 63;
        size_t base = (size_t)(b * SEQ + l * LMSTRIDE) * QKV_N + h * HD + d;
        Z [l*65 + d] = gY[base];
        T1[l*65 + d] = gY[base + CDIM];
    }
    __syncthreads();

    mm64_nt(S, 65, Z, 65, T1, 65, SCALE, tid);
    __syncthreads();
    if (tid < 64) {
        float mx = -1e30f;
        for (int j = 0; j < 64; j++) mx = fmaxf(mx, S[tid*65 + j]);
        float s = 0.f;
        for (int j = 0; j < 64; j++) { float p = __expf(S[tid*65+j] - mx); S[tid*65+j] = p; s += p; }
        float inv = 1.f / s;
        for (int j = 0; j < 64; j++) S[tid*65 + j] *= inv;
    }
    __syncthreads();

    float part = 0.f;
    for (int e = tid; e < 4096; e += 256) {
        int i = e >> 6, j = e & 63;
        float v = S[i*65 + j];
        part += v * v;
    }
    #pragma unroll
    for (int o = 16; o; o >>= 1) part += __shfl_xor_sync(0xffffffffu, part, o);
    if ((tid & 31) == 0) red[tid >> 5] = part;
    __syncthreads();
    float fro2 = red[0]+red[1]+red[2]+red[3]+red[4]+red[5]+red[6]+red[7];
    fro2 = fmaxf(fro2, 1e-12f);
    float invf = 1.f / fro2;

    for (int e = tid; e < 4096; e += 256) {
        int i = e >> 6, j = e & 63;
        Z[j*65 + i] = S[i*65 + j] * invf;
    }
    __syncthreads();

    for (int it = 0; it < 6; it++) {
        mm64_nn(T1, 65, S, 65, Z, 65, tid);
        __syncthreads();
        mm64_nn(T2, 65, Z, 65, T1, 65, tid);
        __syncthreads();
        for (int e = tid; e < 4096; e += 256) {
            int i = e >> 6, j = e & 63;
            Z[i*65 + j] = 2.f * Z[i*65 + j] - T2[i*65 + j];
        }
        __syncthreads();
    }

    for (int e = tid; e < 4096; e += 256) {
        int i = e >> 6, j = e & 63;
        gW2inv[bh*4096 + i*64 + j] = Z[i*65 + j];
    }
}

// ---------------- kernel_3 flash: softmax(q_lm k^T) @ v, partials ------------
__global__ void __launch_bounds__(256) k3_flash()
{
    extern __shared__ float sm3[];
    float* sQ  = sm3;           // 64*64
    float* sK  = sQ + 4096;     // 64*65
    float* sV  = sK + 4160;     // 64*64
    float* sS  = sV + 4096;     // 64*65
    float* m_s = sS + 4160;     // 64
    float* s_s = m_s + 64;
    float* c_s = s_s + 64;

    const int bh = blockIdx.x;
    const int ch = blockIdx.y;
    const int b = bh >> 3, h = bh & 7;
    const int tid = threadIdx.x;
    const int i0 = (tid >> 4) * 4, d0 = (tid & 15) * 4;

    for (int e = tid; e < 4096; e += 256) {
        int l = e >> 6, d = e & 63;
        sQ[l*64 + d] = gY[(size_t)(b * SEQ + l * LMSTRIDE) * QKV_N + h * HD + d];
    }
    if (tid < 64) { m_s[tid] = -1e30f; s_s[tid] = 0.f; }
    float acc[4][4] = {};
    __syncthreads();

    for (int t = 0; t < TILES_PER_CH; t++) {
        int n0 = ch * KEYS_PER_CH + t * 64;
        for (int e = tid; e < 4096; e += 256) {
            int j = e >> 6, d = e & 63;
            size_t base = (size_t)(b * SEQ + n0 + j) * QKV_N + h * HD + d;
            sK[j*65 + d] = gY[base + CDIM];
            sV[j*64 + d] = gY[base + 2*CDIM];
        }
        __syncthreads();
        mm64_nt(sS, 65, sQ, 64, sK, 65, SCALE, tid);
        __syncthreads();
        if (tid < 64) {
            float tmax = -1e30f;
            for (int j = 0; j < 64; j++) tmax = fmaxf(tmax, sS[tid*65 + j]);
            float mnew = fmaxf(m_s[tid], tmax);
            float corr = __expf(m_s[tid] - mnew);
            float rsum = 0.f;
            for (int j = 0; j < 64; j++) {
                float p = __expf(sS[tid*65 + j] - mnew);
                sS[tid*65 + j] = p;
                rsum += p;
            }
            s_s[tid] = s_s[tid] * corr + rsum;
            c_s[tid] = corr;
            m_s[tid] = mnew;
        }
        __syncthreads();
        #pragma unroll
        for (int ii = 0; ii < 4; ii++) {
            int l = i0 + ii;
            float corr = c_s[l];
            float r0 = acc[ii][0]*corr, r1 = acc[ii][1]*corr,
                  r2 = acc[ii][2]*corr, r3 = acc[ii][3]*corr;
            #pragma unroll 8
            for (int j = 0; j < 64; j++) {
                float p = sS[l*65 + j];
                float4 v = *(const float4*)&sV[j*64 + d0];
                r0 += p*v.x; r1 += p*v.y; r2 += p*v.z; r3 += p*v.w;
            }
            acc[ii][0]=r0; acc[ii][1]=r1; acc[ii][2]=r2; acc[ii][3]=r3;
        }
        __syncthreads();
    }

    size_t base = ((size_t)bh * NCH + ch) * 4096;
    #pragma unroll
    for (int ii = 0; ii < 4; ii++)
        *(float4*)&gFp[base + (size_t)(i0+ii)*64 + d0] =
            make_float4(acc[ii][0], acc[ii][1], acc[ii][2], acc[ii][3]);
    if (tid < 64) {
        gMp[(bh*NCH + ch)*64 + tid] = m_s[tid];
        gSp[(bh*NCH + ch)*64 + tid] = s_s[tid];
    }
}

// ---------------- combine flash partials + T = W2inv @ F --------------------
__global__ void __launch_bounds__(256) k3_combine()
{
    __shared__ float wgt[NCH*64];
    __shared__ float sF[64*65];
    __shared__ float sW[64*64];
    const int bh = blockIdx.x;
    const int tid = threadIdx.x;

    if (tid < 64) {
        float M = -1e30f;
        for (int c = 0; c < NCH; c++) M = fmaxf(M, gMp[(bh*NCH + c)*64 + tid]);
        float denom = 0.f;
        for (int c = 0; c < NCH; c++)
            denom += __expf(gMp[(bh*NCH + c)*64 + tid] - M) * gSp[(bh*NCH + c)*64 + tid];
        float invd = 1.f / denom;
        for (int c = 0; c < NCH; c++)
            wgt[c*64 + tid] = __expf(gMp[(bh*NCH + c)*64 + tid] - M) * invd;
    }
    for (int e = tid; e < 4096; e += 256) sW[e] = gW2inv[bh*4096 + e];
    __syncthreads();

    for (int e = tid; e < 4096; e += 256) {
        int l = e >> 6, d = e & 63;
        float f = 0.f;
        for (int c = 0; c < NCH; c++)
            f += gFp[((size_t)bh * NCH + c) * 4096 + e] * wgt[c*64 + l];
        sF[l*65 + d] = f;
    }
    __syncthreads();

    const int i0 = (tid >> 4) * 4, j0 = (tid & 15) * 4;
    float c[4][4] = {};
    #pragma unroll 8
    for (int k = 0; k < 64; k++) {
        float a[4], bv[4];
        #pragma unroll
        for (int ii = 0; ii < 4; ii++) a[ii] = sW[(i0+ii)*64 + k];
        #pragma unroll
        for (int jj = 0; jj < 4; jj++) bv[jj] = sF[k*65 + j0+jj];
        #pragma unroll
        for (int ii = 0; ii < 4; ii++)
            #pragma unroll
            for (int jj = 0; jj < 4; jj++)
                c[ii][jj] += a[ii] * bv[jj];
    }
    #pragma unroll
    for (int ii = 0; ii < 4; ii++)
        #pragma unroll
        for (int jj = 0; jj < 4; jj++)
            gT[bh*4096 + (i0+ii)*64 + j0+jj] = c[ii][jj];
}

// ---------------- kernel_1 @ T -> attention output (fp16 out) ----------------
__global__ void __launch_bounds__(256) k4_out()
{
    extern __shared__ float sm4[];
    float* sK = sm4;            // 64*65 k_lm
    float* sT = sK + 4160;      // 64*64
    float* sQ = sT + 4096;      // 64*64
    float* sS = sQ + 4096;      // 64*65

    const int bh = blockIdx.y;
    const int qt = blockIdx.x;
    const int b = bh >> 3, h = bh & 7;
    const int n0 = qt * 64;
    const int tid = threadIdx.x;

    for (int e = tid; e < 4096; e += 256) {
        int l = e >> 6, d = e & 63;
        sK[l*65 + d] = gY[(size_t)(b * SEQ + l * LMSTRIDE) * QKV_N + CDIM + h * HD + d];
        sT[l*64 + d] = gT[bh*4096 + e];
        sQ[l*64 + d] = gY[(size_t)(b * SEQ + n0 + l) * QKV_N + h * HD + d];
    }
    __syncthreads();

    mm64_nt(sS, 65, sQ, 64, sK, 65, SCALE, tid);
    __syncthreads();
    if (tid < 64) {
        float mx = -1e30f;
        for (int j = 0; j < 64; j++) mx = fmaxf(mx, sS[tid*65 + j]);
        float s = 0.f;
        for (int j = 0; j < 64; j++) { float p = __expf(sS[tid*65+j] - mx); sS[tid*65+j] = p; s += p; }
        float inv = 1.f / s;
        for (int j = 0; j < 64; j++) sS[tid*65 + j] *= inv;
    }
    __syncthreads();

    const int i0 = (tid >> 4) * 4, d0 = (tid & 15) * 4;
    float c[4][4] = {};
    #pragma unroll 8
    for (int l = 0; l < 64; l++) {
        float a[4];
        #pragma unroll
        for (int ii = 0; ii < 4; ii++) a[ii] = sS[(i0+ii)*65 + l];
        float4 tv = *(const float4*)&sT[l*64 + d0];
        #pragma unroll
        for (int ii = 0; ii < 4; ii++) {
            c[ii][0] += a[ii]*tv.x; c[ii][1] += a[ii]*tv.y;
            c[ii][2] += a[ii]*tv.z; c[ii][3] += a[ii]*tv.w;
        }
    }
    #pragma unroll
    for (int ii = 0; ii < 4; ii++) {
        __half2 p0 = __floats2half2_rn(c[ii][0], c[ii][1]);
        __half2 p1 = __floats2half2_rn(c[ii][2], c[ii][3]);
        uint2 o; o.x = *(uint32_t*)&p0; o.y = *(uint32_t*)&p1;
        *(uint2*)&gATh[(size_t)(b * SEQ + n0 + i0 + ii) * CDIM + h * HD + d0] = o;
    }
}

// ---------------- launcher ---------------------------------------------------
extern "C" void kernel_launch(void* const* d_in, const int* in_sizes, int n_in,
                              void* d_out, int out_size)
{
    const float* x     = (const float*)d_in[0];
    const float* Wqkv  = (const float*)d_in[1];
    const float* bqkv  = (const float*)d_in[2];
    const float* Wproj = (const float*)d_in[3];
    const float* bproj = (const float*)d_in[4];
    float* out = (float*)d_out;

    const int SMEM_K2 = 4 * 4160 * 4;                              // 66560
    const int SMEM_K3 = (4096 + 4160 + 4096 + 4160 + 192) * 4;     // 66816
    const int SMEM_K4 = (4160 + 4096 + 4096 + 4160) * 4;           // 66048
    cudaFuncSetAttribute(gemm_h,    cudaFuncAttributeMaxDynamicSharedMemorySize, SMEM_GEMMH);
    cudaFuncSetAttribute(k2_newton, cudaFuncAttributeMaxDynamicSharedMemorySize, SMEM_K2);
    cudaFuncSetAttribute(k3_flash,  cudaFuncAttributeMaxDynamicSharedMemorySize, SMEM_K3);
    cudaFuncSetAttribute(k4_out,    cudaFuncAttributeMaxDynamicSharedMemorySize, SMEM_K4);

    float *pY;
    __half *pXh, *pWqkvh, *pWph, *pATh;
    cudaGetSymbolAddress((void**)&pY,     gY);
    cudaGetSymbolAddress((void**)&pXh,    gXh);
    cudaGetSymbolAddress((void**)&pWqkvh, gWqkvh);
    cudaGetSymbolAddress((void**)&pWph,   gWph);
    cudaGetSymbolAddress((void**)&pATh,   gATh);

    // 0. fp32 -> fp16 conversions
    {
        int nx = BN_TOK * CDIM;
        cvtf2h<<<(nx/8 + 255)/256, 256>>>(x, pXh, nx);
        int nw = QKV_N * CDIM;
        cvtf2h<<<(nw/8 + 255)/256, 256>>>(Wqkv, pWqkvh, nw);
        int np = CDIM * CDIM;
        cvtf2h<<<(np/8 + 255)/256, 256>>>(Wproj, pWph, np);
    }

    // 1. QKV projection: gY = x @ Wqkv^T + bqkv   (fp16 mma + cp.async + ldmatrix)
    gemm_h<<<dim3(QKV_N/128, BN_TOK/128), 256, SMEM_GEMMH>>>(pXh, pWqkvh, bqkv, pY, BN_TOK, QKV_N, CDIM);
    // 2. kernel_2 softmax + Newton inverse
    k2_newton<<<NBH, 256, SMEM_K2>>>();
    // 3. kernel_3 flash softmax @ v (partials), then combine + T = W2inv @ F
    k3_flash<<<dim3(NBH, NCH), 256, SMEM_K3>>>();
    k3_combine<<<NBH, 256>>>();
    // 4. out = softmax(q k_lm^T) @ T  -> gATh (fp16) in [B,N,C] layout
    k4_out<<<dim3(SEQ/64, NBH), 256, SMEM_K4>>>();
    // 5. projection: out = gATh @ Wproj^T + bproj  (fp16 mma)
    gemm_h<<<dim3(CDIM/128, BN_TOK/128), 256, SMEM_GEMMH>>>(pATh, pWph, bproj, out, BN_TOK, CDIM, CDIM);
}

// round 6
// speedup vs baseline: 5.2910x; 1.9485x over previous
#include <cuda_runtime.h>
#include <cuda_fp16.h>
#include <cstdint>

// ---------------- problem constants ----------------
#define BDIM     4
#define SEQ      8192
#define CDIM     512
#define NH       8
#define HD       64
#define NLM      64
#define LMSTRIDE 128           // SEQ / NLM
#define BN_TOK   (BDIM*SEQ)    // 32768
#define QKV_N    (3*CDIM)      // 1536
#define NBH      (BDIM*NH)     // 32
#define NCH      32            // key chunks for kernel_3 flash
#define KEYS_PER_CH (SEQ/NCH)  // 256
#define SCALE    0.125f        // hd^-0.5

// ---------------- device scratch (no runtime allocs allowed) ----------------
__device__ __half gXh[(size_t)BN_TOK * CDIM];    // x in fp16
__device__ __half gWqkvh[QKV_N * CDIM];          // Wqkv in fp16
__device__ __half gWph[CDIM * CDIM];             // Wproj in fp16
__device__ __half gYh[(size_t)BN_TOK * QKV_N];   // qkv activations fp16
__device__ __half gATh[(size_t)BN_TOK * CDIM];   // attention output fp16
__device__ float  gW2inv[NBH*64*64];
__device__ __half gTth[NBH*64*64];               // (W2inv @ F)^T fp16, [bh][hd][lm]
__device__ float  gFp[(size_t)NBH*NCH*64*64];    // flash partial accumulators
__device__ float  gMp[NBH*NCH*64];
__device__ float  gSp[NBH*NCH*64];

// ---------------- ptx helpers ------------------------------------------------
__device__ __forceinline__ uint32_t smem_u32(const void* p) {
    uint32_t a;
    asm("{ .reg .u64 t; cvta.to.shared.u64 t, %1; cvt.u32.u64 %0, t; }" : "=r"(a) : "l"(p));
    return a;
}
__device__ __forceinline__ void mma_f16(float* d, const uint32_t* a, const uint32_t* b) {
    asm volatile(
        "mma.sync.aligned.m16n8k16.row.col.f32.f16.f16.f32 "
        "{%0,%1,%2,%3}, {%4,%5,%6,%7}, {%8,%9}, {%0,%1,%2,%3};"
        : "+f"(d[0]), "+f"(d[1]), "+f"(d[2]), "+f"(d[3])
        : "r"(a[0]), "r"(a[1]), "r"(a[2]), "r"(a[3]),
          "r"(b[0]), "r"(b[1]));
}
__device__ __forceinline__ void ldsm_x4(uint32_t* r, uint32_t addr) {
    asm volatile("ldmatrix.sync.aligned.m8n8.x4.shared.b16 {%0,%1,%2,%3}, [%4];"
                 : "=r"(r[0]), "=r"(r[1]), "=r"(r[2]), "=r"(r[3]) : "r"(addr));
}
__device__ __forceinline__ void ldsm_x4_t(uint32_t* r, uint32_t addr) {
    asm volatile("ldmatrix.sync.aligned.m8n8.x4.trans.shared.b16 {%0,%1,%2,%3}, [%4];"
                 : "=r"(r[0]), "=r"(r[1]), "=r"(r[2]), "=r"(r[3]) : "r"(addr));
}
#define CP_ASYNC16(dst, src) \
    asm volatile("cp.async.cg.shared.global [%0], [%1], 16;" :: "r"(dst), "l"(src) : "memory")
#define CP_COMMIT() asm volatile("cp.async.commit_group;" ::: "memory")
#define CP_WAIT1()  asm volatile("cp.async.wait_group 1;" ::: "memory")
#define CP_WAIT0()  asm volatile("cp.async.wait_group 0;" ::: "memory")

// ---------------- fp32 -> fp16 conversion ------------------------------------
__global__ void __launch_bounds__(256) cvtf2h(const float* __restrict__ s,
                                              __half* __restrict__ d, int n)
{
    int i = (blockIdx.x * blockDim.x + threadIdx.x) * 8;
    if (i < n) {
        float4 a = *(const float4*)(s + i);
        float4 b = *(const float4*)(s + i + 4);
        __half2 h0 = __floats2half2_rn(a.x, a.y);
        __half2 h1 = __floats2half2_rn(a.z, a.w);
        __half2 h2 = __floats2half2_rn(b.x, b.y);
        __half2 h3 = __floats2half2_rn(b.z, b.w);
        uint4 o;
        o.x = *(uint32_t*)&h0; o.y = *(uint32_t*)&h1;
        o.z = *(uint32_t*)&h2; o.w = *(uint32_t*)&h3;
        *(uint4*)(d + i) = o;
    }
}

// ---------------- fp16 tensor-core GEMM: C = A[M,K]h @ B[N,K]h^T + bias -----
#define STG_BYTES 32768          // 16KB A + 16KB B per stage
#define SMEM_GEMMH (3 * STG_BYTES)

__device__ __forceinline__ void stage_copy(uint32_t sbase, const __half* A,
                                           const __half* B, int bm, int bn,
                                           int K, int k0, int tid)
{
    #pragma unroll
    for (int i = 0; i < 4; i++) {
        int lin = tid + i * 256;
        int row = lin >> 3;
        int c   = lin & 7;
        uint32_t dA = sbase + row * 128 + ((c ^ (row & 7)) << 4);
        CP_ASYNC16(dA, A + (size_t)(bm + row) * K + k0 + c * 8);
        uint32_t dB = sbase + 16384 + row * 128 + ((c ^ (row & 7)) << 4);
        CP_ASYNC16(dB, B + (size_t)(bn + row) * K + k0 + c * 8);
    }
}

__global__ void __launch_bounds__(256) gemm_h(const __half* __restrict__ A,
                                              const __half* __restrict__ B,
                                              const float* __restrict__ bias,
                                              void* __restrict__ Cv,
                                              int M, int N, int K, int half_out)
{
    extern __shared__ __align__(128) char smg[];
    const uint32_t sb = smem_u32(smg);

    const int bm = blockIdx.y * 128;
    const int bn = blockIdx.x * 128;
    const int tid  = threadIdx.x;
    const int lane = tid & 31;
    const int warp = tid >> 5;
    const int wm = (warp & 1) * 64;
    const int wn = (warp >> 1) * 32;
    const int g = lane >> 2;
    const int c = lane & 3;
    const int lrow = lane & 15;
    const int lhalf = lane >> 4;

    float acc[4][4][4];
    #pragma unroll
    for (int mi = 0; mi < 4; mi++)
        #pragma unroll
        for (int t = 0; t < 4; t++)
            #pragma unroll
            for (int r = 0; r < 4; r++) acc[mi][t][r] = 0.f;

    const int KT = K >> 6;

    stage_copy(sb, A, B, bm, bn, K, 0, tid);
    CP_COMMIT();
    stage_copy(sb + STG_BYTES, A, B, bm, bn, K, 64, tid);
    CP_COMMIT();

    for (int kt = 0; kt < KT; kt++) {
        CP_WAIT1();
        __syncthreads();

        if (kt + 2 < KT)
            stage_copy(sb + ((kt + 2) % 3) * STG_BYTES, A, B, bm, bn, K, (kt + 2) * 64, tid);
        CP_COMMIT();

        const uint32_t aBase = sb + (kt % 3) * STG_BYTES;
        const uint32_t bBase = aBase + 16384;

        #pragma unroll
        for (int ks = 0; ks < 4; ks++) {
            uint32_t af[4][4], bf[2][4];
            #pragma unroll
            for (int mi = 0; mi < 4; mi++) {
                const int row = wm + mi * 16 + lrow;
                const int ch  = (ks * 2 + lhalf) ^ (row & 7);
                ldsm_x4(af[mi], aBase + row * 128 + (ch << 4));
            }
            #pragma unroll
            for (int nj = 0; nj < 2; nj++) {
                const int row = wn + nj * 16 + lrow;
                const int ch  = (ks * 2 + lhalf) ^ (row & 7);
                ldsm_x4(bf[nj], bBase + row * 128 + (ch << 4));
            }
            #pragma unroll
            for (int mi = 0; mi < 4; mi++) {
                #pragma unroll
                for (int t = 0; t < 4; t++) {
                    const int nj = t >> 1, sub = t & 1;
                    uint32_t b2[2] = { bf[nj][sub], bf[nj][sub + 2] };
                    mma_f16(acc[mi][t], af[mi], b2);
                }
            }
        }
    }

    if (half_out) {
        __half* C = (__half*)Cv;
        #pragma unroll
        for (int mi = 0; mi < 4; mi++) {
            const int row = bm + wm + mi * 16 + g;
            #pragma unroll
            for (int t = 0; t < 4; t++) {
                const int col = bn + wn + (t >> 1) * 16 + (t & 1) * 8 + 2 * c;
                const float b0 = bias[col], b1 = bias[col + 1];
                __half2 o0 = __floats2half2_rn(acc[mi][t][0] + b0, acc[mi][t][1] + b1);
                __half2 o1 = __floats2half2_rn(acc[mi][t][2] + b0, acc[mi][t][3] + b1);
                *(uint32_t*)(C + (size_t)row * N + col)       = *(uint32_t*)&o0;
                *(uint32_t*)(C + (size_t)(row + 8) * N + col) = *(uint32_t*)&o1;
            }
        }
    } else {
        float* C = (float*)Cv;
        #pragma unroll
        for (int mi = 0; mi < 4; mi++) {
            const int row = bm + wm + mi * 16 + g;
            #pragma unroll
            for (int t = 0; t < 4; t++) {
                const int col = bn + wn + (t >> 1) * 16 + (t & 1) * 8 + 2 * c;
                const float b0 = bias[col], b1 = bias[col + 1];
                float2 o0 = make_float2(acc[mi][t][0] + b0, acc[mi][t][1] + b1);
                float2 o1 = make_float2(acc[mi][t][2] + b0, acc[mi][t][3] + b1);
                *(float2*)(C + (size_t)row * N + col)       = o0;
                *(float2*)(C + (size_t)(row + 8) * N + col) = o1;
            }
        }
    }
}

// ---------------- small 64x64 fp32 helpers (k2/combine only) -----------------
__device__ __forceinline__ void mm64_nt(float* C, int ldc,
                                        const float* A, int lda,
                                        const float* B, int ldb,
                                        float scale, int tid)
{
    const int i0 = (tid >> 4) * 4, j0 = (tid & 15) * 4;
    float c[4][4] = {};
    #pragma unroll 8
    for (int d = 0; d < 64; d++) {
        float a[4], bv[4];
        #pragma unroll
        for (int ii = 0; ii < 4; ii++) a[ii]  = A[(i0+ii)*lda + d];
        #pragma unroll
        for (int jj = 0; jj < 4; jj++) bv[jj] = B[(j0+jj)*ldb + d];
        #pragma unroll
        for (int ii = 0; ii < 4; ii++)
            #pragma unroll
            for (int jj = 0; jj < 4; jj++)
                c[ii][jj] += a[ii] * bv[jj];
    }
    #pragma unroll
    for (int ii = 0; ii < 4; ii++)
        #pragma unroll
        for (int jj = 0; jj < 4; jj++)
            C[(i0+ii)*ldc + j0+jj] = scale * c[ii][jj];
}

__device__ __forceinline__ void mm64_nn(float* C, int ldc,
                                        const float* A, int lda,
                                        const float* B, int ldb, int tid)
{
    const int i0 = (tid >> 4) * 4, j0 = (tid & 15) * 4;
    float c[4][4] = {};
    #pragma unroll 8
    for (int k = 0; k < 64; k++) {
        float a[4], bv[4];
        #pragma unroll
        for (int ii = 0; ii < 4; ii++) a[ii]  = A[(i0+ii)*lda + k];
        #pragma unroll
        for (int jj = 0; jj < 4; jj++) bv[jj] = B[k*ldb + j0+jj];
        #pragma unroll
        for (int ii = 0; ii < 4; ii++)
            #pragma unroll
            for (int jj = 0; jj < 4; jj++)
                c[ii][jj] += a[ii] * bv[jj];
    }
    #pragma unroll
    for (int ii = 0; ii < 4; ii++)
        #pragma unroll
        for (int jj = 0; jj < 4; jj++)
            C[(i0+ii)*ldc + j0+jj] = c[ii][jj];
}

// ---------------- kernel_2 softmax + Newton pseudo-inverse -------------------
__global__ void __launch_bounds__(256) k2_newton()
{
    extern __shared__ float sm2[];
    float* S  = sm2;
    float* Z  = S  + 4160;
    float* T1 = Z  + 4160;
    float* T2 = T1 + 4160;
    __shared__ float red[8];

    const int bh = blockIdx.x;
    const int b = bh >> 3, h = bh & 7;
    const int tid = threadIdx.x;

    for (int e = tid; e < 4096; e += 256) {
        int l = e >> 6, d = e & 63;
        size_t base = (size_t)(b * SEQ + l * LMSTRIDE) * QKV_N + h * HD + d;
        Z [l*65 + d] = __half2float(gYh[base]);
        T1[l*65 + d] = __half2float(gYh[base + CDIM]);
    }
    __syncthreads();

    mm64_nt(S, 65, Z, 65, T1, 65, SCALE, tid);
    __syncthreads();
    if (tid < 64) {
        float mx = -1e30f;
        for (int j = 0; j < 64; j++) mx = fmaxf(mx, S[tid*65 + j]);
        float s = 0.f;
        for (int j = 0; j < 64; j++) { float p = __expf(S[tid*65+j] - mx); S[tid*65+j] = p; s += p; }
        float inv = 1.f / s;
        for (int j = 0; j < 64; j++) S[tid*65 + j] *= inv;
    }
    __syncthreads();

    float part = 0.f;
    for (int e = tid; e < 4096; e += 256) {
        int i = e >> 6, j = e & 63;
        float v = S[i*65 + j];
        part += v * v;
    }
    #pragma unroll
    for (int o = 16; o; o >>= 1) part += __shfl_xor_sync(0xffffffffu, part, o);
    if ((tid & 31) == 0) red[tid >> 5] = part;
    __syncthreads();
    float fro2 = red[0]+red[1]+red[2]+red[3]+red[4]+red[5]+red[6]+red[7];
    fro2 = fmaxf(fro2, 1e-12f);
    float invf = 1.f / fro2;

    for (int e = tid; e < 4096; e += 256) {
        int i = e >> 6, j = e & 63;
        Z[j*65 + i] = S[i*65 + j] * invf;
    }
    __syncthreads();

    for (int it = 0; it < 6; it++) {
        mm64_nn(T1, 65, S, 65, Z, 65, tid);
        __syncthreads();
        mm64_nn(T2, 65, Z, 65, T1, 65, tid);
        __syncthreads();
        for (int e = tid; e < 4096; e += 256) {
            int i = e >> 6, j = e & 63;
            Z[i*65 + j] = 2.f * Z[i*65 + j] - T2[i*65 + j];
        }
        __syncthreads();
    }

    for (int e = tid; e < 4096; e += 256) {
        int i = e >> 6, j = e & 63;
        gW2inv[bh*4096 + i*64 + j] = Z[i*65 + j];
    }
}

// ---------------- kernel_3 flash (tensor-core): partials ---------------------
// block 128 threads (4 warps of 16 rows), grid (NBH, NCH)
#define K3_SMEM (8192 + 2*16384)  // Q + 2-stage K/V

__global__ void __launch_bounds__(128) k3_flash()
{
    extern __shared__ __align__(128) char sm3[];
    const uint32_t sQ  = smem_u32(sm3);
    const uint32_t sKV = sQ + 8192;

    const int bh = blockIdx.x;
    const int ch = blockIdx.y;
    const int b = bh >> 3, h = bh & 7;
    const int tid = threadIdx.x;
    const int lane = tid & 31;
    const int w = tid >> 5;
    const int g = lane >> 2, c = lane & 3;
    const int lrow = lane & 15, lhalf = lane >> 4;
    const int n0base = ch * KEYS_PER_CH;

    // stage Q (landmarks) + tile 0 (group 0), tile 1 (group 1)
    for (int i = tid; i < 512; i += 128) {
        int row = i >> 3, c4 = i & 7;
        CP_ASYNC16(sQ + row*128 + ((c4 ^ (row&7)) << 4),
                   gYh + ((size_t)(b*SEQ + row*LMSTRIDE))*QKV_N + h*HD + c4*8);
    }
    #pragma unroll
    for (int st = 0; st < 2; st++) {
        uint32_t base = sKV + st * 16384;
        for (int i = tid; i < 1024; i += 128) {
            int sel = i >> 9;
            int row = (i >> 3) & 63;
            int c4 = i & 7;
            CP_ASYNC16(base + sel*8192 + row*128 + ((c4 ^ (row&7)) << 4),
                       gYh + ((size_t)(b*SEQ + n0base + st*64 + row))*QKV_N
                           + (sel ? 2*CDIM : CDIM) + h*HD + c4*8);
        }
        CP_COMMIT();
    }

    float m0 = -1e30f, m1 = -1e30f, s0 = 0.f, s1 = 0.f;
    float oc[8][4];
    #pragma unroll
    for (int u = 0; u < 8; u++) { oc[u][0]=oc[u][1]=oc[u][2]=oc[u][3]=0.f; }

    for (int t = 0; t < 4; t++) {
        CP_WAIT1();
        __syncthreads();
        const uint32_t kb = sKV + (t & 1) * 16384;
        const uint32_t vb = kb + 8192;

        // S = Q @ K^T
        float sc[8][4];
        #pragma unroll
        for (int u = 0; u < 8; u++) { sc[u][0]=sc[u][1]=sc[u][2]=sc[u][3]=0.f; }
        #pragma unroll
        for (int ks = 0; ks < 4; ks++) {
            uint32_t af[4];
            const int qr = w*16 + lrow;
            ldsm_x4(af, sQ + qr*128 + (((ks*2+lhalf) ^ (qr&7)) << 4));
            #pragma unroll
            for (int nj = 0; nj < 4; nj++) {
                uint32_t bf[4];
                const int kr = nj*16 + lrow;
                ldsm_x4(bf, kb + kr*128 + (((ks*2+lhalf) ^ (kr&7)) << 4));
                uint32_t b2a[2] = { bf[0], bf[2] };
                mma_f16(sc[nj*2+0], af, b2a);
                uint32_t b2b[2] = { bf[1], bf[3] };
                mma_f16(sc[nj*2+1], af, b2b);
            }
        }
        // online softmax
        float tm0 = -1e30f, tm1 = -1e30f;
        #pragma unroll
        for (int u = 0; u < 8; u++) {
            sc[u][0]*=SCALE; sc[u][1]*=SCALE; sc[u][2]*=SCALE; sc[u][3]*=SCALE;
            tm0 = fmaxf(tm0, fmaxf(sc[u][0], sc[u][1]));
            tm1 = fmaxf(tm1, fmaxf(sc[u][2], sc[u][3]));
        }
        tm0 = fmaxf(tm0, __shfl_xor_sync(0xffffffffu, tm0, 1));
        tm0 = fmaxf(tm0, __shfl_xor_sync(0xffffffffu, tm0, 2));
        tm1 = fmaxf(tm1, __shfl_xor_sync(0xffffffffu, tm1, 1));
        tm1 = fmaxf(tm1, __shfl_xor_sync(0xffffffffu, tm1, 2));
        const float mn0 = fmaxf(m0, tm0), mn1 = fmaxf(m1, tm1);
        const float cr0 = __expf(m0 - mn0), cr1 = __expf(m1 - mn1);
        float rs0 = 0.f, rs1 = 0.f;
        uint32_t pa[4][4];
        #pragma unroll
        for (int u = 0; u < 8; u++) {
            float p0 = __expf(sc[u][0]-mn0), p1 = __expf(sc[u][1]-mn0);
            float p2 = __expf(sc[u][2]-mn1), p3 = __expf(sc[u][3]-mn1);
            rs0 += p0 + p1; rs1 += p2 + p3;
            __half2 hA = __floats2half2_rn(p0, p1);
            __half2 hB = __floats2half2_rn(p2, p3);
            pa[u>>1][(u&1)*2+0] = *(uint32_t*)&hA;
            pa[u>>1][(u&1)*2+1] = *(uint32_t*)&hB;
        }
        rs0 += __shfl_xor_sync(0xffffffffu, rs0, 1);
        rs0 += __shfl_xor_sync(0xffffffffu, rs0, 2);
        rs1 += __shfl_xor_sync(0xffffffffu, rs1, 1);
        rs1 += __shfl_xor_sync(0xffffffffu, rs1, 2);
        s0 = s0*cr0 + rs0; s1 = s1*cr1 + rs1;
        m0 = mn0; m1 = mn1;
        #pragma unroll
        for (int u = 0; u < 8; u++) {
            oc[u][0]*=cr0; oc[u][1]*=cr0; oc[u][2]*=cr1; oc[u][3]*=cr1;
        }
        // O += P @ V   (B fragments from K-major V via trans ldmatrix)
        #pragma unroll
        for (int ks = 0; ks < 4; ks++) {
            #pragma unroll
            for (int nj = 0; nj < 4; nj++) {
                uint32_t bf[4];
                const int rk = ks*16 + (lane&7) + ((lane>>4)&1)*8;
                const int cn = nj*2 + ((lane>>3)&1);
                ldsm_x4_t(bf, vb + rk*128 + (((cn ^ (rk&7))) << 4));
                uint32_t b2a[2] = { bf[0], bf[2] };
                mma_f16(oc[nj*2+0], pa[ks], b2a);
                uint32_t b2b[2] = { bf[1], bf[3] };
                mma_f16(oc[nj*2+1], pa[ks], b2b);
            }
        }
        __syncthreads();
        if (t + 2 < 4) {
            uint32_t base = sKV + (t & 1) * 16384;
            int n0 = n0base + (t + 2) * 64;
            for (int i = tid; i < 1024; i += 128) {
                int sel = i >> 9;
                int row = (i >> 3) & 63;
                int c4 = i & 7;
                CP_ASYNC16(base + sel*8192 + row*128 + ((c4 ^ (row&7)) << 4),
                           gYh + ((size_t)(b*SEQ + n0 + row))*QKV_N
                               + (sel ? 2*CDIM : CDIM) + h*HD + c4*8);
            }
        }
        CP_COMMIT();
    }

    const size_t fbase = ((size_t)bh*NCH + ch)*4096;
    const int r0a = w*16 + g, r1a = r0a + 8;
    #pragma unroll
    for (int u = 0; u < 8; u++) {
        int col = u*8 + 2*c;
        *(float2*)&gFp[fbase + (size_t)r0a*64 + col] = make_float2(oc[u][0], oc[u][1]);
        *(float2*)&gFp[fbase + (size_t)r1a*64 + col] = make_float2(oc[u][2], oc[u][3]);
    }
    if (c == 0) {
        gMp[(bh*NCH+ch)*64 + r0a] = m0;
        gMp[(bh*NCH+ch)*64 + r1a] = m1;
        gSp[(bh*NCH+ch)*64 + r0a] = s0;
        gSp[(bh*NCH+ch)*64 + r1a] = s1;
    }
}

// ---------------- combine flash partials + T^T = (W2inv @ F)^T ---------------
__global__ void __launch_bounds__(256) k3_combine()
{
    __shared__ float wgt[NCH*64];
    __shared__ float sF[64*65];
    __shared__ float sW[64*64];
    const int bh = blockIdx.x;
    const int tid = threadIdx.x;

    if (tid < 64) {
        float M = -1e30f;
        for (int c = 0; c < NCH; c++) M = fmaxf(M, gMp[(bh*NCH + c)*64 + tid]);
        float denom = 0.f;
        for (int c = 0; c < NCH; c++)
            denom += __expf(gMp[(bh*NCH + c)*64 + tid] - M) * gSp[(bh*NCH + c)*64 + tid];
        float invd = 1.f / denom;
        for (int c = 0; c < NCH; c++)
            wgt[c*64 + tid] = __expf(gMp[(bh*NCH + c)*64 + tid] - M) * invd;
    }
    for (int e = tid; e < 4096; e += 256) sW[e] = gW2inv[bh*4096 + e];
    __syncthreads();

    for (int e = tid; e < 4096; e += 256) {
        int l = e >> 6, d = e & 63;
        float f = 0.f;
        for (int c = 0; c < NCH; c++)
            f += gFp[((size_t)bh * NCH + c) * 4096 + e] * wgt[c*64 + l];
        sF[l*65 + d] = f;
    }
    __syncthreads();

    const int i0 = (tid >> 4) * 4, j0 = (tid & 15) * 4;
    float cc[4][4] = {};
    #pragma unroll 8
    for (int k = 0; k < 64; k++) {
        float a[4], bv[4];
        #pragma unroll
        for (int ii = 0; ii < 4; ii++) a[ii] = sW[(i0+ii)*64 + k];
        #pragma unroll
        for (int jj = 0; jj < 4; jj++) bv[jj] = sF[k*65 + j0+jj];
        #pragma unroll
        for (int ii = 0; ii < 4; ii++)
            #pragma unroll
            for (int jj = 0; jj < 4; jj++)
                cc[ii][jj] += a[ii] * bv[jj];
    }
    // write transposed fp16: gTth[bh][hd=j][lm=i]
    #pragma unroll
    for (int ii = 0; ii < 4; ii++)
        #pragma unroll
        for (int jj = 0; jj < 4; jj++)
            gTth[bh*4096 + (j0+jj)*64 + (i0+ii)] = __float2half(cc[ii][jj]);
}

// ---------------- kernel_1 @ T (tensor-core) -> gATh -------------------------
// block 128 threads (4 warps of 16 rows), grid (SEQ/64, NBH)
#define K4_SMEM (3*8192)

__global__ void __launch_bounds__(128) k4_out()
{
    extern __shared__ __align__(128) char sm4[];
    const uint32_t sQ = smem_u32(sm4);
    const uint32_t sK = sQ + 8192;
    const uint32_t sT = sK + 8192;

    const int qt = blockIdx.x;
    const int bh = blockIdx.y;
    const int b = bh >> 3, h = bh & 7;
    const int n0 = qt * 64;
    const int tid = threadIdx.x;
    const int lane = tid & 31;
    const int w = tid >> 5;
    const int g = lane >> 2, c = lane & 3;
    const int lrow = lane & 15, lhalf = lane >> 4;

    for (int i = tid; i < 512; i += 128) {
        int row = i >> 3, c4 = i & 7;
        uint32_t swz = (uint32_t)((c4 ^ (row & 7)) << 4);
        CP_ASYNC16(sQ + row*128 + swz,
                   gYh + ((size_t)(b*SEQ + n0 + row))*QKV_N + h*HD + c4*8);
        CP_ASYNC16(sK + row*128 + swz,
                   gYh + ((size_t)(b*SEQ + row*LMSTRIDE))*QKV_N + CDIM + h*HD + c4*8);
        CP_ASYNC16(sT + row*128 + swz,
                   gTth + bh*4096 + row*64 + c4*8);
    }
    CP_COMMIT();
    CP_WAIT0();
    __syncthreads();

    // S = Q @ K_lm^T
    float sc[8][4];
    #pragma unroll
    for (int u = 0; u < 8; u++) { sc[u][0]=sc[u][1]=sc[u][2]=sc[u][3]=0.f; }
    #pragma unroll
    for (int ks = 0; ks < 4; ks++) {
        uint32_t af[4];
        const int qr = w*16 + lrow;
        ldsm_x4(af, sQ + qr*128 + (((ks*2+lhalf) ^ (qr&7)) << 4));
        #pragma unroll
        for (int nj = 0; nj < 4; nj++) {
            uint32_t bf[4];
            const int kr = nj*16 + lrow;
            ldsm_x4(bf, sK + kr*128 + (((ks*2+lhalf) ^ (kr&7)) << 4));
            uint32_t b2a[2] = { bf[0], bf[2] };
            mma_f16(sc[nj*2+0], af, b2a);
            uint32_t b2b[2] = { bf[1], bf[3] };
            mma_f16(sc[nj*2+1], af, b2b);
        }
    }
    // exact softmax
    float tm0 = -1e30f, tm1 = -1e30f;
    #pragma unroll
    for (int u = 0; u < 8; u++) {
        sc[u][0]*=SCALE; sc[u][1]*=SCALE; sc[u][2]*=SCALE; sc[u][3]*=SCALE;
        tm0 = fmaxf(tm0, fmaxf(sc[u][0], sc[u][1]));
        tm1 = fmaxf(tm1, fmaxf(sc[u][2], sc[u][3]));
    }
    tm0 = fmaxf(tm0, __shfl_xor_sync(0xffffffffu, tm0, 1));
    tm0 = fmaxf(tm0, __shfl_xor_sync(0xffffffffu, tm0, 2));
    tm1 = fmaxf(tm1, __shfl_xor_sync(0xffffffffu, tm1, 1));
    tm1 = fmaxf(tm1, __shfl_xor_sync(0xffffffffu, tm1, 2));
    float rs0 = 0.f, rs1 = 0.f;
    uint32_t pa[4][4];
    #pragma unroll
    for (int u = 0; u < 8; u++) {
        float p0 = __expf(sc[u][0]-tm0), p1 = __expf(sc[u][1]-tm0);
        float p2 = __expf(sc[u][2]-tm1), p3 = __expf(sc[u][3]-tm1);
        rs0 += p0 + p1; rs1 += p2 + p3;
        __half2 hA = __floats2half2_rn(p0, p1);
        __half2 hB = __floats2half2_rn(p2, p3);
        pa[u>>1][(u&1)*2+0] = *(uint32_t*)&hA;
        pa[u>>1][(u&1)*2+1] = *(uint32_t*)&hB;
    }
    rs0 += __shfl_xor_sync(0xffffffffu, rs0, 1);
    rs0 += __shfl_xor_sync(0xffffffffu, rs0, 2);
    rs1 += __shfl_xor_sync(0xffffffffu, rs1, 1);
    rs1 += __shfl_xor_sync(0xffffffffu, rs1, 2);
    const float inv0 = 1.f / rs0, inv1 = 1.f / rs1;

    // O = P @ T   (B fragments from Tt[hd][lm], n-major -> non-trans ldmatrix)
    float oc[8][4];
    #pragma unroll
    for (int u = 0; u < 8; u++) { oc[u][0]=oc[u][1]=oc[u][2]=oc[u][3]=0.f; }
    #pragma unroll
    for (int ks = 0; ks < 4; ks++) {
        #pragma unroll
        for (int nj = 0; nj < 4; nj++) {
            uint32_t bf[4];
            const int tr = nj*16 + lrow;
            ldsm_x4(bf, sT + tr*128 + (((ks*2+lhalf) ^ (tr&7)) << 4));
            uint32_t b2a[2] = { bf[0], bf[2] };
            mma_f16(oc[nj*2+0], pa[ks], b2a);
            uint32_t b2b[2] = { bf[1], bf[3] };
            mma_f16(oc[nj*2+1], pa[ks], b2b);
        }
    }

    const int r0a = w*16 + g;
    #pragma unroll
    for (int u = 0; u < 8; u++) {
        int col = u*8 + 2*c;
        __half2 hA = __floats2half2_rn(oc[u][0]*inv0, oc[u][1]*inv0);
        __half2 hB = __floats2half2_rn(oc[u][2]*inv1, oc[u][3]*inv1);
        *(uint32_t*)&gATh[((size_t)(b*SEQ + n0 + r0a))*CDIM + h*HD + col]     = *(uint32_t*)&hA;
        *(uint32_t*)&gATh[((size_t)(b*SEQ + n0 + r0a + 8))*CDIM + h*HD + col] = *(uint32_t*)&hB;
    }
}

// ---------------- launcher ---------------------------------------------------
extern "C" void kernel_launch(void* const* d_in, const int* in_sizes, int n_in,
                              void* d_out, int out_size)
{
    const float* x     = (const float*)d_in[0];
    const float* Wqkv  = (const float*)d_in[1];
    const float* bqkv  = (const float*)d_in[2];
    const float* Wproj = (const float*)d_in[3];
    const float* bproj = (const float*)d_in[4];
    float* out = (float*)d_out;

    const int SMEM_K2 = 4 * 4160 * 4;
    cudaFuncSetAttribute(gemm_h,    cudaFuncAttributeMaxDynamicSharedMemorySize, SMEM_GEMMH);
    cudaFuncSetAttribute(k2_newton, cudaFuncAttributeMaxDynamicSharedMemorySize, SMEM_K2);
    cudaFuncSetAttribute(k3_flash,  cudaFuncAttributeMaxDynamicSharedMemorySize, K3_SMEM);
    cudaFuncSetAttribute(k4_out,    cudaFuncAttributeMaxDynamicSharedMemorySize, K4_SMEM);

    __half *pXh, *pWqkvh, *pWph, *pYh, *pATh;
    cudaGetSymbolAddress((void**)&pXh,    gXh);
    cudaGetSymbolAddress((void**)&pWqkvh, gWqkvh);
    cudaGetSymbolAddress((void**)&pWph,   gWph);
    cudaGetSymbolAddress((void**)&pYh,    gYh);
    cudaGetSymbolAddress((void**)&pATh,   gATh);

    // 0. fp32 -> fp16 conversions
    {
        int nx = BN_TOK * CDIM;
        cvtf2h<<<(nx/8 + 255)/256, 256>>>(x, pXh, nx);
        int nw = QKV_N * CDIM;
        cvtf2h<<<(nw/8 + 255)/256, 256>>>(Wqkv, pWqkvh, nw);
        int np = CDIM * CDIM;
        cvtf2h<<<(np/8 + 255)/256, 256>>>(Wproj, pWph, np);
    }

    // 1. QKV projection -> fp16 gYh
    gemm_h<<<dim3(QKV_N/128, BN_TOK/128), 256, SMEM_GEMMH>>>(pXh, pWqkvh, bqkv, pYh, BN_TOK, QKV_N, CDIM, 1);
    // 2. kernel_2 softmax + Newton inverse
    k2_newton<<<NBH, 256, SMEM_K2>>>();
    // 3. flash partials (tensor cores), combine + T^T fp16
    k3_flash<<<dim3(NBH, NCH), 128, K3_SMEM>>>();
    k3_combine<<<NBH, 256>>>();
    // 4. out = softmax(q k_lm^T) @ T (tensor cores) -> gATh fp16
    k4_out<<<dim3(SEQ/64, NBH), 128, K4_SMEM>>>();
    // 5. projection: out = gATh @ Wproj^T + bproj (fp32 out)
    gemm_h<<<dim3(CDIM/128, BN_TOK/128), 256, SMEM_GEMMH>>>(pATh, pWph, bproj, out, BN_TOK, CDIM, CDIM, 0);
}